// round 1
// baseline (speedup 1.0000x reference)
#include <cuda_runtime.h>
#include <math.h>

#define D_MODEL   2048
#define NUM_HEADS 16
#define HEAD      128
#define FAN       4
#define QKV_OUT   (3 * D_MODEL + FAN * D_MODEL)   // 14336
#define HIDDEN    (FAN * D_MODEL)                 // 8192
#define BB        2
#define TT        2048
#define BT        (BB * TT)                       // 4096

// ---------------- scratch (device globals: allocation-guard compliant) -----
__device__ float g_x[(size_t)BT * D_MODEL];       // LN(inputs)      33.5 MB
__device__ float g_qkv[(size_t)BT * QKV_OUT];     // qkv_hidden     235 MB

// ---------------- helpers --------------------------------------------------
__device__ __forceinline__ float warp_sum(float v) {
    #pragma unroll
    for (int o = 16; o > 0; o >>= 1) v += __shfl_xor_sync(0xffffffffu, v, o);
    return v;
}

// ---------------- 1) LayerNorm over input rows (2048 wide) ----------------
__global__ void ln_input_kernel(const float* __restrict__ in, float* __restrict__ out) {
    int row = blockIdx.x;
    const float4* src = (const float4*)(in + (size_t)row * D_MODEL);
    float4*       dst = (float4*)(out + (size_t)row * D_MODEL);

    float4 v[2];
    float s = 0.f, sq = 0.f;
    #pragma unroll
    for (int i = 0; i < 2; i++) {
        v[i] = src[threadIdx.x + i * 256];
        s  += v[i].x + v[i].y + v[i].z + v[i].w;
        sq += v[i].x * v[i].x + v[i].y * v[i].y + v[i].z * v[i].z + v[i].w * v[i].w;
    }
    __shared__ float sh_s[8], sh_q[8];
    int lane = threadIdx.x & 31, wid = threadIdx.x >> 5;
    s = warp_sum(s); sq = warp_sum(sq);
    if (lane == 0) { sh_s[wid] = s; sh_q[wid] = sq; }
    __syncthreads();
    if (wid == 0) {
        float a = (lane < 8) ? sh_s[lane] : 0.f;
        float b = (lane < 8) ? sh_q[lane] : 0.f;
        a = warp_sum(a); b = warp_sum(b);
        if (lane == 0) { sh_s[0] = a; sh_q[0] = b; }
    }
    __syncthreads();
    float mean = sh_s[0] * (1.f / D_MODEL);
    float var  = sh_q[0] * (1.f / D_MODEL) - mean * mean;
    float r    = rsqrtf(var + 1e-5f);
    #pragma unroll
    for (int i = 0; i < 2; i++) {
        float4 o;
        o.x = (v[i].x - mean) * r; o.y = (v[i].y - mean) * r;
        o.z = (v[i].z - mean) * r; o.w = (v[i].w - mean) * r;
        dst[threadIdx.x + i * 256] = o;
    }
}

// ---------------- 2) SGEMM 128x128x8, 8x8 per thread -----------------------
// C[M,N] = A[M,K] * B[K,N] + bias[N] (+ res[M,N]), all row-major.
template<bool ADD_RES>
__global__ __launch_bounds__(256, 2)
void sgemm_kernel(const float* __restrict__ A, int lda,
                  const float* __restrict__ B, int ldb,
                  float* __restrict__ C, int ldc,
                  const float* __restrict__ bias,
                  const float* __restrict__ res,
                  int K) {
    __shared__ float As[8][128];
    __shared__ float Bs[8][128];

    int tx = threadIdx.x & 15, ty = threadIdx.x >> 4;
    int bm = blockIdx.y * 128, bn = blockIdx.x * 128;
    A += (size_t)bm * lda;
    B += bn;

    float acc[8][8];
    #pragma unroll
    for (int i = 0; i < 8; i++)
        #pragma unroll
        for (int j = 0; j < 8; j++) acc[i][j] = 0.f;

    int arow = threadIdx.x >> 1;
    int acol = (threadIdx.x & 1) * 4;
    int brow = threadIdx.x >> 5;
    int bcol = (threadIdx.x & 31) * 4;

    for (int k0 = 0; k0 < K; k0 += 8) {
        float4 av = *(const float4*)(A + (size_t)arow * lda + k0 + acol);
        float4 bv = *(const float4*)(B + (size_t)(k0 + brow) * ldb + bcol);
        As[acol + 0][arow] = av.x;
        As[acol + 1][arow] = av.y;
        As[acol + 2][arow] = av.z;
        As[acol + 3][arow] = av.w;
        *(float4*)&Bs[brow][bcol] = bv;
        __syncthreads();

        #pragma unroll
        for (int k = 0; k < 8; k++) {
            float a[8], b[8];
            *(float4*)(a)     = *(const float4*)&As[k][ty * 8];
            *(float4*)(a + 4) = *(const float4*)&As[k][ty * 8 + 4];
            *(float4*)(b)     = *(const float4*)&Bs[k][tx * 8];
            *(float4*)(b + 4) = *(const float4*)&Bs[k][tx * 8 + 4];
            #pragma unroll
            for (int i = 0; i < 8; i++)
                #pragma unroll
                for (int j = 0; j < 8; j++)
                    acc[i][j] += a[i] * b[j];
        }
        __syncthreads();
    }

    // epilogue (vectorized)
    #pragma unroll
    for (int i = 0; i < 8; i++) {
        int row = bm + ty * 8 + i;
        #pragma unroll
        for (int j4 = 0; j4 < 2; j4++) {
            int col = bn + tx * 8 + j4 * 4;
            float4 bia = *(const float4*)(bias + col);
            float4 o;
            o.x = acc[i][j4 * 4 + 0] + bia.x;
            o.y = acc[i][j4 * 4 + 1] + bia.y;
            o.z = acc[i][j4 * 4 + 2] + bia.z;
            o.w = acc[i][j4 * 4 + 3] + bia.w;
            if (ADD_RES) {
                float4 rr = *(const float4*)(res + (size_t)row * ldc + col);
                o.x += rr.x; o.y += rr.y; o.z += rr.z; o.w += rr.w;
            }
            *(float4*)(C + (size_t)row * ldc + col) = o;
        }
    }
}

// ---------------- 3a) per-head LN on q and k (rows of 128) -----------------
__global__ void head_ln_kernel(float* __restrict__ qkv) {
    int gw   = (blockIdx.x * blockDim.x + threadIdx.x) >> 5;  // 0..131071
    int lane = threadIdx.x & 31;
    int seg   = gw >> 16;        // 0 = q, 1 = k
    int r     = gw & 65535;
    int token = r >> 4;
    int h     = r & 15;
    float* base = qkv + (size_t)token * QKV_OUT + seg * D_MODEL + h * HEAD;
    float4 v = ((float4*)base)[lane];
    float s = warp_sum(v.x + v.y + v.z + v.w) * (1.f / HEAD);
    float d0 = v.x - s, d1 = v.y - s, d2 = v.z - s, d3 = v.w - s;
    float var = warp_sum(d0 * d0 + d1 * d1 + d2 * d2 + d3 * d3) * (1.f / HEAD);
    float rr = rsqrtf(var + 1e-5f);
    ((float4*)base)[lane] = make_float4(d0 * rr, d1 * rr, d2 * rr, d3 * rr);
}

// ---------------- 3b) exact GELU in-place on hidden segment ----------------
__global__ void gelu_kernel(float* __restrict__ qkv) {
    int idx = blockIdx.x * blockDim.x + threadIdx.x;   // over BT * HIDDEN/4
    int row = idx >> 11;            // / (HIDDEN/4 = 2048)
    int c4  = idx & 2047;
    float4* p = (float4*)(qkv + (size_t)row * QKV_OUT + 3 * D_MODEL) + c4;
    float4 v = *p;
    const float k = 0.70710678118654752f;
    v.x = 0.5f * v.x * (1.f + erff(v.x * k));
    v.y = 0.5f * v.y * (1.f + erff(v.y * k));
    v.z = 0.5f * v.z * (1.f + erff(v.z * k));
    v.w = 0.5f * v.w * (1.f + erff(v.w * k));
    *p = v;
}

// ---------------- 4) causal flash attention, adds into out -----------------
#define BQ 64
#define BK 64
#define QK_STRIDE 68
#define V_STRIDE 132
#define FLASH_SMEM_FLOATS (128 * QK_STRIDE * 2 + BK * V_STRIDE + BQ * QK_STRIDE)
#define FLASH_SMEM_BYTES  (FLASH_SMEM_FLOATS * 4)

__global__ __launch_bounds__(256, 1)
void flash_kernel(const float* __restrict__ qkv, float* __restrict__ out) {
    extern __shared__ float sm[];
    float* Qst = sm;                          // [128][68]  (k-major)
    float* Kst = Qst + 128 * QK_STRIDE;       // [128][68]
    float* Vs  = Kst + 128 * QK_STRIDE;       // [64][132]
    float* Ps  = Vs + BK * V_STRIDE;          // [64][68]

    int qt = gridDim.x - 1 - blockIdx.x;      // longest tiles first
    int bh = blockIdx.y;
    int b = bh >> 4, h = bh & 15;
    int tid = threadIdx.x;
    int tx = tid & 15, ty = tid >> 4;

    const float* qbase = qkv + (size_t)b * TT * QKV_OUT + h * HEAD;
    const float* kbase = qbase + D_MODEL;
    const float* vbase = qbase + 2 * D_MODEL;

    // load Q tile transposed: Qst[k][m]
    {
        int c4 = tid & 31, m0 = tid >> 5;
        #pragma unroll
        for (int it = 0; it < 8; it++) {
            int m = m0 + it * 8;
            float4 v = *(const float4*)(qbase + (size_t)(qt * BQ + m) * QKV_OUT + c4 * 4);
            Qst[(c4 * 4 + 0) * QK_STRIDE + m] = v.x;
            Qst[(c4 * 4 + 1) * QK_STRIDE + m] = v.y;
            Qst[(c4 * 4 + 2) * QK_STRIDE + m] = v.z;
            Qst[(c4 * 4 + 3) * QK_STRIDE + m] = v.w;
        }
    }

    float O[4][8];
    float M[4], L[4];
    #pragma unroll
    for (int i = 0; i < 4; i++) {
        M[i] = -INFINITY; L[i] = 0.f;
        #pragma unroll
        for (int j = 0; j < 8; j++) O[i][j] = 0.f;
    }

    const float scale = 0.08838834764831845f;  // 1/sqrt(128)

    for (int kt = 0; kt <= qt; kt++) {
        // load K (transposed) and V tiles
        {
            int c4 = tid & 31, m0 = tid >> 5;
            #pragma unroll
            for (int it = 0; it < 8; it++) {
                int m = m0 + it * 8;
                size_t grow = (size_t)(kt * BK + m) * QKV_OUT;
                float4 kv = *(const float4*)(kbase + grow + c4 * 4);
                Kst[(c4 * 4 + 0) * QK_STRIDE + m] = kv.x;
                Kst[(c4 * 4 + 1) * QK_STRIDE + m] = kv.y;
                Kst[(c4 * 4 + 2) * QK_STRIDE + m] = kv.z;
                Kst[(c4 * 4 + 3) * QK_STRIDE + m] = kv.w;
                float4 vv = *(const float4*)(vbase + grow + c4 * 4);
                *(float4*)&Vs[m * V_STRIDE + c4 * 4] = vv;
            }
        }
        __syncthreads();

        // S = Q K^T (4x4 per thread)
        float s[4][4];
        #pragma unroll
        for (int i = 0; i < 4; i++)
            #pragma unroll
            for (int j = 0; j < 4; j++) s[i][j] = 0.f;

        #pragma unroll 4
        for (int k = 0; k < 128; k++) {
            float4 aq = *(const float4*)(Qst + k * QK_STRIDE + ty * 4);
            float4 bk = *(const float4*)(Kst + k * QK_STRIDE + tx * 4);
            float a_[4] = {aq.x, aq.y, aq.z, aq.w};
            float b_[4] = {bk.x, bk.y, bk.z, bk.w};
            #pragma unroll
            for (int i = 0; i < 4; i++)
                #pragma unroll
                for (int j = 0; j < 4; j++)
                    s[i][j] += a_[i] * b_[j];
        }

        int qrow0 = qt * BQ + ty * 4;
        int kcol0 = kt * BK + tx * 4;

        #pragma unroll
        for (int i = 0; i < 4; i++) {
            #pragma unroll
            for (int j = 0; j < 4; j++) {
                if (kcol0 + j > qrow0 + i) s[i][j] = -INFINITY;
                else                       s[i][j] *= scale;
            }
            // row max across the 16 tx lanes (butterfly stays in 16-lane group)
            float tmax = fmaxf(fmaxf(s[i][0], s[i][1]), fmaxf(s[i][2], s[i][3]));
            #pragma unroll
            for (int o = 1; o < 16; o <<= 1)
                tmax = fmaxf(tmax, __shfl_xor_sync(0xffffffffu, tmax, o));

            float nm   = fmaxf(M[i], tmax);
            float corr = __expf(M[i] - nm);
            float psum = 0.f;
            #pragma unroll
            for (int j = 0; j < 4; j++) {
                float p = __expf(s[i][j] - nm);
                s[i][j] = p;
                psum += p;
            }
            #pragma unroll
            for (int o = 1; o < 16; o <<= 1)
                psum += __shfl_xor_sync(0xffffffffu, psum, o);

            L[i] = L[i] * corr + psum;
            M[i] = nm;
            #pragma unroll
            for (int j = 0; j < 8; j++) O[i][j] *= corr;
            #pragma unroll
            for (int j = 0; j < 4; j++)
                Ps[(ty * 4 + i) * QK_STRIDE + tx * 4 + j] = s[i][j];
        }
        __syncthreads();

        // O += P V (4x8 per thread)
        #pragma unroll 2
        for (int kk = 0; kk < BK; kk++) {
            float p_[4];
            #pragma unroll
            for (int i = 0; i < 4; i++) p_[i] = Ps[(ty * 4 + i) * QK_STRIDE + kk];
            float4 v0 = *(const float4*)(Vs + kk * V_STRIDE + tx * 8);
            float4 v1 = *(const float4*)(Vs + kk * V_STRIDE + tx * 8 + 4);
            float v_[8] = {v0.x, v0.y, v0.z, v0.w, v1.x, v1.y, v1.z, v1.w};
            #pragma unroll
            for (int i = 0; i < 4; i++)
                #pragma unroll
                for (int j = 0; j < 8; j++)
                    O[i][j] += p_[i] * v_[j];
        }
        __syncthreads();
    }

    // epilogue: out += O / L
    #pragma unroll
    for (int i = 0; i < 4; i++) {
        float inv = 1.f / L[i];
        size_t row = (size_t)(b * TT + qt * BQ + ty * 4 + i);
        float* orow = out + row * D_MODEL + h * HEAD + tx * 8;
        #pragma unroll
        for (int j = 0; j < 8; j++)
            orow[j] += O[i][j] * inv;
    }
}

// ---------------- launch ----------------------------------------------------
extern "C" void kernel_launch(void* const* d_in, const int* in_sizes, int n_in,
                              void* d_out, int out_size) {
    const float* inputs = (const float*)d_in[0];
    const float* W_qkv  = (const float*)d_in[1];
    const float* b_qkv  = (const float*)d_in[2];
    const float* W_mlp  = (const float*)d_in[3];
    const float* b_mlp  = (const float*)d_in[4];
    float* out = (float*)d_out;

    void *pgx, *pgq;
    cudaGetSymbolAddress(&pgx, g_x);
    cudaGetSymbolAddress(&pgq, g_qkv);
    float* gx = (float*)pgx;
    float* gq = (float*)pgq;

    // 1) LN(inputs)
    ln_input_kernel<<<BT, 256>>>(inputs, gx);

    // 2) qkv_hidden = x @ W_qkv + b_qkv    (M=4096, N=14336, K=2048)
    sgemm_kernel<false><<<dim3(QKV_OUT / 128, BT / 128), 256>>>(
        gx, D_MODEL, W_qkv, QKV_OUT, gq, QKV_OUT, b_qkv, nullptr, D_MODEL);

    // 3) per-head LN on q,k; GELU on hidden (both in place)
    head_ln_kernel<<<(BT * NUM_HEADS * 2) / 8, 256>>>(gq);
    gelu_kernel<<<(BT * (HIDDEN / 4)) / 256, 256>>>(gq);

    // 4) out = gelu(hidden) @ W_mlp + b_mlp + inputs   (M=4096, N=2048, K=8192)
    sgemm_kernel<true><<<dim3(D_MODEL / 128, BT / 128), 256>>>(
        gq + 3 * D_MODEL, QKV_OUT, W_mlp, D_MODEL, out, D_MODEL, b_mlp, inputs, HIDDEN);

    // 5) out += attention(q, k, v)
    cudaFuncSetAttribute(flash_kernel, cudaFuncAttributeMaxDynamicSharedMemorySize,
                         FLASH_SMEM_BYTES);
    flash_kernel<<<dim3(TT / BQ, BB * NUM_HEADS), 256, FLASH_SMEM_BYTES>>>(gq, out);
}

// round 3
// speedup vs baseline: 2.1482x; 2.1482x over previous
#include <cuda_runtime.h>
#include <cuda_bf16.h>
#include <math.h>
#include <stdint.h>

#define D_MODEL   2048
#define NUM_HEADS 16
#define HEAD      128
#define FAN       4
#define QKV_OUT   (3 * D_MODEL + FAN * D_MODEL)   // 14336
#define HIDDEN    (FAN * D_MODEL)                 // 8192
#define BB        2
#define TT        2048
#define BT        (BB * TT)                       // 4096

// ---------------- scratch (device globals: allocation-guard compliant) -----
__device__ float g_x[(size_t)BT * D_MODEL];       // LN(inputs)      33.5 MB
__device__ float g_qkv[(size_t)BT * QKV_OUT];     // qkv_hidden     235 MB

// ---------------- helpers --------------------------------------------------
__device__ __forceinline__ float warp_sum(float v) {
    #pragma unroll
    for (int o = 16; o > 0; o >>= 1) v += __shfl_xor_sync(0xffffffffu, v, o);
    return v;
}

__device__ __forceinline__ uint32_t smem_u32(const void* p) {
    uint32_t a;
    asm("{ .reg .u64 t; cvta.to.shared.u64 t, %1; cvt.u32.u64 %0, t; }"
        : "=r"(a) : "l"(p));
    return a;
}

__device__ __forceinline__ void ldsm_x4(uint32_t& r0, uint32_t& r1,
                                        uint32_t& r2, uint32_t& r3, uint32_t addr) {
    asm volatile("ldmatrix.sync.aligned.m8n8.x4.shared.b16 {%0,%1,%2,%3}, [%4];"
                 : "=r"(r0), "=r"(r1), "=r"(r2), "=r"(r3) : "r"(addr));
}

__device__ __forceinline__ void mma_bf16(float& d0, float& d1, float& d2, float& d3,
                                         uint32_t a0, uint32_t a1, uint32_t a2, uint32_t a3,
                                         uint32_t b0, uint32_t b1) {
    asm volatile(
        "mma.sync.aligned.m16n8k16.row.col.f32.bf16.bf16.f32 "
        "{%0,%1,%2,%3}, {%4,%5,%6,%7}, {%8,%9}, {%0,%1,%2,%3};"
        : "+f"(d0), "+f"(d1), "+f"(d2), "+f"(d3)
        : "r"(a0), "r"(a1), "r"(a2), "r"(a3), "r"(b0), "r"(b1));
}

__device__ __forceinline__ uint32_t pack_hi(float x, float y) {
    __nv_bfloat162 h = __float22bfloat162_rn(make_float2(x, y));
    return *(uint32_t*)&h;
}
__device__ __forceinline__ uint32_t pack_lo(float x, float y, uint32_t hi) {
    __nv_bfloat162 h = *(__nv_bfloat162*)&hi;
    __nv_bfloat162 l = __float22bfloat162_rn(make_float2(
        x - __bfloat162float(h.x), y - __bfloat162float(h.y)));
    return *(uint32_t*)&l;
}

// ---------------- 1) LayerNorm over input rows (2048 wide) ----------------
__global__ void ln_input_kernel(const float* __restrict__ in, float* __restrict__ out) {
    int row = blockIdx.x;
    const float4* src = (const float4*)(in + (size_t)row * D_MODEL);
    float4*       dst = (float4*)(out + (size_t)row * D_MODEL);

    float4 v[2];
    float s = 0.f, sq = 0.f;
    #pragma unroll
    for (int i = 0; i < 2; i++) {
        v[i] = src[threadIdx.x + i * 256];
        s  += v[i].x + v[i].y + v[i].z + v[i].w;
        sq += v[i].x * v[i].x + v[i].y * v[i].y + v[i].z * v[i].z + v[i].w * v[i].w;
    }
    __shared__ float sh_s[8], sh_q[8];
    int lane = threadIdx.x & 31, wid = threadIdx.x >> 5;
    s = warp_sum(s); sq = warp_sum(sq);
    if (lane == 0) { sh_s[wid] = s; sh_q[wid] = sq; }
    __syncthreads();
    if (wid == 0) {
        float a = (lane < 8) ? sh_s[lane] : 0.f;
        float b = (lane < 8) ? sh_q[lane] : 0.f;
        a = warp_sum(a); b = warp_sum(b);
        if (lane == 0) { sh_s[0] = a; sh_q[0] = b; }
    }
    __syncthreads();
    float mean = sh_s[0] * (1.f / D_MODEL);
    float var  = sh_q[0] * (1.f / D_MODEL) - mean * mean;
    float r    = rsqrtf(var + 1e-5f);
    #pragma unroll
    for (int i = 0; i < 2; i++) {
        float4 o;
        o.x = (v[i].x - mean) * r; o.y = (v[i].y - mean) * r;
        o.z = (v[i].z - mean) * r; o.w = (v[i].w - mean) * r;
        dst[threadIdx.x + i * 256] = o;
    }
}

// ============================================================================
// 2) Tensor-core split-bf16 GEMM via mma.sync (m16n8k16, bf16 -> f32)
//    C[M,N] = A[M,K] @ W[K,N] + bias (+ res).  CTA 128x128, kblock=32.
//    Every fp32 split hi+lo bf16; 3 MMAs (hh, hl, lh) per position.
// ============================================================================
#define BKB 32                  // k per block (bf16 elements)
#define SROW 40                 // smem row stride in bf16 (80 B)
#define TILE_U32 (128 * SROW / 2)

template<bool ADD_RES>
__global__ __launch_bounds__(256, 2)
void tc_gemm_kernel(const float* __restrict__ A, int lda,
                    const float* __restrict__ W, int ldb,
                    float* __restrict__ C, int ldc,
                    const float* __restrict__ bias,
                    const float* __restrict__ res,
                    int K) {
    __shared__ uint32_t sm[4 * TILE_U32];
    __nv_bfloat16* sAh = (__nv_bfloat16*)(sm);
    __nv_bfloat16* sAl = (__nv_bfloat16*)(sm + TILE_U32);
    __nv_bfloat16* sBh = (__nv_bfloat16*)(sm + 2 * TILE_U32);
    __nv_bfloat16* sBl = (__nv_bfloat16*)(sm + 3 * TILE_U32);
    const uint32_t sAh_b = smem_u32(sAh);
    const uint32_t sAl_b = smem_u32(sAl);
    const uint32_t sBh_b = smem_u32(sBh);
    const uint32_t sBl_b = smem_u32(sBl);

    const int tid = threadIdx.x;
    const int l = tid & 31, w = tid >> 5;
    const int wm = (w & 3) * 32;         // warp m offset
    const int wn = (w >> 2) * 64;        // warp n offset
    const int bm = blockIdx.x * 128, bn = blockIdx.y * 128;

    // loader indices
    const int am = tid >> 1;             // A row (0..127)
    const int ah = tid & 1;              // A k-half (16 floats each)
    const int bnn = tid & 127;           // B n (0..127)
    const int bkh = tid >> 7;            // B k-half

    float acc[2][8][4];
    #pragma unroll
    for (int mt = 0; mt < 2; mt++)
        #pragma unroll
        for (int nt = 0; nt < 8; nt++)
            #pragma unroll
            for (int e = 0; e < 4; e++) acc[mt][nt][e] = 0.f;

    // ldmatrix addresses (lane-dependent, loop-invariant except k-step)
    // A: rows m0..15 (+16B col half), within warp m-tile
    const uint32_t a_row = wm + (l & 15);
    const uint32_t a_coloff = (uint32_t)(l >> 4) * 16;
    // B: rows n (l&7) + ((l>>4)&1)*8, col half ((l>>3)&1)*16
    const uint32_t b_rowoff = wn + (l & 7) + ((l >> 4) & 1) * 8;
    const uint32_t b_coloff = (uint32_t)((l >> 3) & 1) * 16;

    const int nkb = K / BKB;
    for (int kb = 0; kb < nkb; kb++) {
        const int k0 = kb * BKB;

        // ---- load A tile: [128 m][32 k], hi/lo split ----
        {
            const float* ap = A + (size_t)(bm + am) * lda + k0 + ah * 16;
            float4 v0 = *(const float4*)(ap);
            float4 v1 = *(const float4*)(ap + 4);
            float4 v2 = *(const float4*)(ap + 8);
            float4 v3 = *(const float4*)(ap + 12);
            uint4 H0, H1, L0, L1;
            H0.x = pack_hi(v0.x, v0.y); L0.x = pack_lo(v0.x, v0.y, H0.x);
            H0.y = pack_hi(v0.z, v0.w); L0.y = pack_lo(v0.z, v0.w, H0.y);
            H0.z = pack_hi(v1.x, v1.y); L0.z = pack_lo(v1.x, v1.y, H0.z);
            H0.w = pack_hi(v1.z, v1.w); L0.w = pack_lo(v1.z, v1.w, H0.w);
            H1.x = pack_hi(v2.x, v2.y); L1.x = pack_lo(v2.x, v2.y, H1.x);
            H1.y = pack_hi(v2.z, v2.w); L1.y = pack_lo(v2.z, v2.w, H1.y);
            H1.z = pack_hi(v3.x, v3.y); L1.z = pack_lo(v3.x, v3.y, H1.z);
            H1.w = pack_hi(v3.z, v3.w); L1.w = pack_lo(v3.z, v3.w, H1.w);
            int o = am * SROW + ah * 16;
            *(uint4*)(sAh + o)     = H0;
            *(uint4*)(sAh + o + 8) = H1;
            *(uint4*)(sAl + o)     = L0;
            *(uint4*)(sAl + o + 8) = L1;
        }
        // ---- load B tile: sB[n][k] = W[k0+k][bn+n], hi/lo split ----
        {
            const float* bp = W + (size_t)(k0 + bkh * 16) * ldb + bn + bnn;
            float b[16];
            #pragma unroll
            for (int j = 0; j < 16; j++) b[j] = bp[(size_t)j * ldb];
            uint4 H0, H1, L0, L1;
            H0.x = pack_hi(b[0],  b[1]);  L0.x = pack_lo(b[0],  b[1],  H0.x);
            H0.y = pack_hi(b[2],  b[3]);  L0.y = pack_lo(b[2],  b[3],  H0.y);
            H0.z = pack_hi(b[4],  b[5]);  L0.z = pack_lo(b[4],  b[5],  H0.z);
            H0.w = pack_hi(b[6],  b[7]);  L0.w = pack_lo(b[6],  b[7],  H0.w);
            H1.x = pack_hi(b[8],  b[9]);  L1.x = pack_lo(b[8],  b[9],  H1.x);
            H1.y = pack_hi(b[10], b[11]); L1.y = pack_lo(b[10], b[11], H1.y);
            H1.z = pack_hi(b[12], b[13]); L1.z = pack_lo(b[12], b[13], H1.z);
            H1.w = pack_hi(b[14], b[15]); L1.w = pack_lo(b[14], b[15], H1.w);
            int o = bnn * SROW + bkh * 16;
            *(uint4*)(sBh + o)     = H0;
            *(uint4*)(sBh + o + 8) = H1;
            *(uint4*)(sBl + o)     = L0;
            *(uint4*)(sBl + o + 8) = L1;
        }
        __syncthreads();

        #pragma unroll
        for (int ks = 0; ks < 2; ks++) {
            // A fragments (hi & lo) for 2 m-tiles
            uint32_t ah_[2][4], al_[2][4];
            #pragma unroll
            for (int mt = 0; mt < 2; mt++) {
                uint32_t off = (a_row + mt * 16) * (SROW * 2) + ks * 32 + a_coloff;
                ldsm_x4(ah_[mt][0], ah_[mt][1], ah_[mt][2], ah_[mt][3], sAh_b + off);
                ldsm_x4(al_[mt][0], al_[mt][1], al_[mt][2], al_[mt][3], sAl_b + off);
            }
            // B in 4 n-pairs
            #pragma unroll
            for (int p = 0; p < 4; p++) {
                uint32_t off = (b_rowoff + p * 16) * (SROW * 2) + ks * 32 + b_coloff;
                uint32_t bh0, bh1, bh2, bh3, bl0, bl1, bl2, bl3;
                ldsm_x4(bh0, bh1, bh2, bh3, sBh_b + off);
                ldsm_x4(bl0, bl1, bl2, bl3, sBl_b + off);
                #pragma unroll
                for (int mt = 0; mt < 2; mt++) {
                    float* d0 = acc[mt][p * 2];
                    float* d1 = acc[mt][p * 2 + 1];
                    mma_bf16(d0[0], d0[1], d0[2], d0[3],
                             ah_[mt][0], ah_[mt][1], ah_[mt][2], ah_[mt][3], bh0, bh1);
                    mma_bf16(d0[0], d0[1], d0[2], d0[3],
                             ah_[mt][0], ah_[mt][1], ah_[mt][2], ah_[mt][3], bl0, bl1);
                    mma_bf16(d0[0], d0[1], d0[2], d0[3],
                             al_[mt][0], al_[mt][1], al_[mt][2], al_[mt][3], bh0, bh1);
                    mma_bf16(d1[0], d1[1], d1[2], d1[3],
                             ah_[mt][0], ah_[mt][1], ah_[mt][2], ah_[mt][3], bh2, bh3);
                    mma_bf16(d1[0], d1[1], d1[2], d1[3],
                             ah_[mt][0], ah_[mt][1], ah_[mt][2], ah_[mt][3], bl2, bl3);
                    mma_bf16(d1[0], d1[1], d1[2], d1[3],
                             al_[mt][0], al_[mt][1], al_[mt][2], al_[mt][3], bh2, bh3);
                }
            }
        }
        __syncthreads();
    }

    // ---- epilogue ----
    #pragma unroll
    for (int mt = 0; mt < 2; mt++) {
        int row0 = bm + wm + mt * 16 + (l >> 2);
        #pragma unroll
        for (int nt = 0; nt < 8; nt++) {
            int col = bn + wn + nt * 8 + (l & 3) * 2;
            float b0 = bias[col], b1 = bias[col + 1];
            float* d = acc[mt][nt];
            float2 o0 = make_float2(d[0] + b0, d[1] + b1);
            float2 o1 = make_float2(d[2] + b0, d[3] + b1);
            if (ADD_RES) {
                float2 r0 = *(const float2*)(res + (size_t)row0 * ldc + col);
                float2 r1 = *(const float2*)(res + (size_t)(row0 + 8) * ldc + col);
                o0.x += r0.x; o0.y += r0.y;
                o1.x += r1.x; o1.y += r1.y;
            }
            *(float2*)(C + (size_t)row0 * ldc + col) = o0;
            *(float2*)(C + (size_t)(row0 + 8) * ldc + col) = o1;
        }
    }
}

// ---------------- 3a) per-head LN on q and k (rows of 128) -----------------
__global__ void head_ln_kernel(float* __restrict__ qkv) {
    int gw   = (blockIdx.x * blockDim.x + threadIdx.x) >> 5;
    int lane = threadIdx.x & 31;
    int seg   = gw >> 16;        // 0 = q, 1 = k
    int r     = gw & 65535;
    int token = r >> 4;
    int h     = r & 15;
    float* base = qkv + (size_t)token * QKV_OUT + seg * D_MODEL + h * HEAD;
    float4 v = ((float4*)base)[lane];
    float s = warp_sum(v.x + v.y + v.z + v.w) * (1.f / HEAD);
    float d0 = v.x - s, d1 = v.y - s, d2 = v.z - s, d3 = v.w - s;
    float var = warp_sum(d0 * d0 + d1 * d1 + d2 * d2 + d3 * d3) * (1.f / HEAD);
    float rr = rsqrtf(var + 1e-5f);
    ((float4*)base)[lane] = make_float4(d0 * rr, d1 * rr, d2 * rr, d3 * rr);
}

// ---------------- 3b) exact GELU in-place on hidden segment ----------------
__global__ void gelu_kernel(float* __restrict__ qkv) {
    int idx = blockIdx.x * blockDim.x + threadIdx.x;
    int row = idx >> 11;
    int c4  = idx & 2047;
    float4* p = (float4*)(qkv + (size_t)row * QKV_OUT + 3 * D_MODEL) + c4;
    float4 v = *p;
    const float k = 0.70710678118654752f;
    v.x = 0.5f * v.x * (1.f + erff(v.x * k));
    v.y = 0.5f * v.y * (1.f + erff(v.y * k));
    v.z = 0.5f * v.z * (1.f + erff(v.z * k));
    v.w = 0.5f * v.w * (1.f + erff(v.w * k));
    *p = v;
}

// ---------------- 4) causal flash attention, adds into out -----------------
#define BQ 64
#define BK 64
#define QK_STRIDE 68
#define V_STRIDE 132
#define FLASH_SMEM_FLOATS (128 * QK_STRIDE * 2 + BK * V_STRIDE + BQ * QK_STRIDE)
#define FLASH_SMEM_BYTES  (FLASH_SMEM_FLOATS * 4)

__global__ __launch_bounds__(256, 1)
void flash_kernel(const float* __restrict__ qkv, float* __restrict__ out) {
    extern __shared__ float sm[];
    float* Qst = sm;
    float* Kst = Qst + 128 * QK_STRIDE;
    float* Vs  = Kst + 128 * QK_STRIDE;
    float* Ps  = Vs + BK * V_STRIDE;

    int qt = gridDim.x - 1 - blockIdx.x;
    int bh = blockIdx.y;
    int b = bh >> 4, h = bh & 15;
    int tid = threadIdx.x;
    int tx = tid & 15, ty = tid >> 4;

    const float* qbase = qkv + (size_t)b * TT * QKV_OUT + h * HEAD;
    const float* kbase = qbase + D_MODEL;
    const float* vbase = qbase + 2 * D_MODEL;

    {
        int c4 = tid & 31, m0 = tid >> 5;
        #pragma unroll
        for (int it = 0; it < 8; it++) {
            int m = m0 + it * 8;
            float4 v = *(const float4*)(qbase + (size_t)(qt * BQ + m) * QKV_OUT + c4 * 4);
            Qst[(c4 * 4 + 0) * QK_STRIDE + m] = v.x;
            Qst[(c4 * 4 + 1) * QK_STRIDE + m] = v.y;
            Qst[(c4 * 4 + 2) * QK_STRIDE + m] = v.z;
            Qst[(c4 * 4 + 3) * QK_STRIDE + m] = v.w;
        }
    }

    float O[4][8];
    float M[4], L[4];
    #pragma unroll
    for (int i = 0; i < 4; i++) {
        M[i] = -INFINITY; L[i] = 0.f;
        #pragma unroll
        for (int j = 0; j < 8; j++) O[i][j] = 0.f;
    }

    const float scale = 0.08838834764831845f;

    for (int kt = 0; kt <= qt; kt++) {
        {
            int c4 = tid & 31, m0 = tid >> 5;
            #pragma unroll
            for (int it = 0; it < 8; it++) {
                int m = m0 + it * 8;
                size_t grow = (size_t)(kt * BK + m) * QKV_OUT;
                float4 kv = *(const float4*)(kbase + grow + c4 * 4);
                Kst[(c4 * 4 + 0) * QK_STRIDE + m] = kv.x;
                Kst[(c4 * 4 + 1) * QK_STRIDE + m] = kv.y;
                Kst[(c4 * 4 + 2) * QK_STRIDE + m] = kv.z;
                Kst[(c4 * 4 + 3) * QK_STRIDE + m] = kv.w;
                float4 vv = *(const float4*)(vbase + grow + c4 * 4);
                *(float4*)&Vs[m * V_STRIDE + c4 * 4] = vv;
            }
        }
        __syncthreads();

        float s[4][4];
        #pragma unroll
        for (int i = 0; i < 4; i++)
            #pragma unroll
            for (int j = 0; j < 4; j++) s[i][j] = 0.f;

        #pragma unroll 4
        for (int k = 0; k < 128; k++) {
            float4 aq = *(const float4*)(Qst + k * QK_STRIDE + ty * 4);
            float4 bk = *(const float4*)(Kst + k * QK_STRIDE + tx * 4);
            float a_[4] = {aq.x, aq.y, aq.z, aq.w};
            float b_[4] = {bk.x, bk.y, bk.z, bk.w};
            #pragma unroll
            for (int i = 0; i < 4; i++)
                #pragma unroll
                for (int j = 0; j < 4; j++)
                    s[i][j] += a_[i] * b_[j];
        }

        int qrow0 = qt * BQ + ty * 4;
        int kcol0 = kt * BK + tx * 4;

        #pragma unroll
        for (int i = 0; i < 4; i++) {
            #pragma unroll
            for (int j = 0; j < 4; j++) {
                if (kcol0 + j > qrow0 + i) s[i][j] = -INFINITY;
                else                       s[i][j] *= scale;
            }
            float tmax = fmaxf(fmaxf(s[i][0], s[i][1]), fmaxf(s[i][2], s[i][3]));
            #pragma unroll
            for (int o = 1; o < 16; o <<= 1)
                tmax = fmaxf(tmax, __shfl_xor_sync(0xffffffffu, tmax, o));

            float nm   = fmaxf(M[i], tmax);
            float corr = __expf(M[i] - nm);
            float psum = 0.f;
            #pragma unroll
            for (int j = 0; j < 4; j++) {
                float p = __expf(s[i][j] - nm);
                s[i][j] = p;
                psum += p;
            }
            #pragma unroll
            for (int o = 1; o < 16; o <<= 1)
                psum += __shfl_xor_sync(0xffffffffu, psum, o);

            L[i] = L[i] * corr + psum;
            M[i] = nm;
            #pragma unroll
            for (int j = 0; j < 8; j++) O[i][j] *= corr;
            #pragma unroll
            for (int j = 0; j < 4; j++)
                Ps[(ty * 4 + i) * QK_STRIDE + tx * 4 + j] = s[i][j];
        }
        __syncthreads();

        #pragma unroll 2
        for (int kk = 0; kk < BK; kk++) {
            float p_[4];
            #pragma unroll
            for (int i = 0; i < 4; i++) p_[i] = Ps[(ty * 4 + i) * QK_STRIDE + kk];
            float4 v0 = *(const float4*)(Vs + kk * V_STRIDE + tx * 8);
            float4 v1 = *(const float4*)(Vs + kk * V_STRIDE + tx * 8 + 4);
            float v_[8] = {v0.x, v0.y, v0.z, v0.w, v1.x, v1.y, v1.z, v1.w};
            #pragma unroll
            for (int i = 0; i < 4; i++)
                #pragma unroll
                for (int j = 0; j < 8; j++)
                    O[i][j] += p_[i] * v_[j];
        }
        __syncthreads();
    }

    #pragma unroll
    for (int i = 0; i < 4; i++) {
        float inv = 1.f / L[i];
        size_t row = (size_t)(b * TT + qt * BQ + ty * 4 + i);
        float* orow = out + row * D_MODEL + h * HEAD + tx * 8;
        #pragma unroll
        for (int j = 0; j < 8; j++)
            orow[j] += O[i][j] * inv;
    }
}

// ---------------- launch ----------------------------------------------------
extern "C" void kernel_launch(void* const* d_in, const int* in_sizes, int n_in,
                              void* d_out, int out_size) {
    const float* inputs = (const float*)d_in[0];
    const float* W_qkv  = (const float*)d_in[1];
    const float* b_qkv  = (const float*)d_in[2];
    const float* W_mlp  = (const float*)d_in[3];
    const float* b_mlp  = (const float*)d_in[4];
    float* out = (float*)d_out;

    void *pgx, *pgq;
    cudaGetSymbolAddress(&pgx, g_x);
    cudaGetSymbolAddress(&pgq, g_qkv);
    float* gx = (float*)pgx;
    float* gq = (float*)pgq;

    cudaFuncSetAttribute(flash_kernel,
                         cudaFuncAttributeMaxDynamicSharedMemorySize, FLASH_SMEM_BYTES);

    // 1) LN(inputs)
    ln_input_kernel<<<BT, 256>>>(inputs, gx);

    // 2) qkv_hidden = x @ W_qkv + b_qkv    (M=4096, N=14336, K=2048)
    tc_gemm_kernel<false><<<dim3(BT / 128, QKV_OUT / 128), 256>>>(
        gx, D_MODEL, W_qkv, QKV_OUT, gq, QKV_OUT, b_qkv, nullptr, D_MODEL);

    // 3) per-head LN on q,k; GELU on hidden (both in place)
    head_ln_kernel<<<(BT * NUM_HEADS * 2) / 8, 256>>>(gq);
    gelu_kernel<<<(BT * (HIDDEN / 4)) / 256, 256>>>(gq);

    // 4) out = gelu(hidden) @ W_mlp + b_mlp + inputs   (M=4096, N=2048, K=8192)
    tc_gemm_kernel<true><<<dim3(BT / 128, D_MODEL / 128), 256>>>(
        gq + 3 * D_MODEL, QKV_OUT, W_mlp, D_MODEL, out, D_MODEL, b_mlp, inputs, HIDDEN);

    // 5) out += attention(q, k, v)
    flash_kernel<<<dim3(TT / BQ, BB * NUM_HEADS), 256, FLASH_SMEM_BYTES>>>(gq, out);
}

// round 4
// speedup vs baseline: 3.0578x; 1.4234x over previous
#include <cuda_runtime.h>
#include <cuda_bf16.h>
#include <math.h>
#include <stdint.h>

#define D_MODEL   2048
#define NUM_HEADS 16
#define HEAD      128
#define FAN       4
#define QKV_OUT   (3 * D_MODEL + FAN * D_MODEL)   // 14336
#define HIDDEN    (FAN * D_MODEL)                 // 8192
#define BB        2
#define TT        2048
#define BT        (BB * TT)                       // 4096

// ---------------- scratch (device globals) ---------------------------------
__device__ float         g_qkv[(size_t)BT * QKV_OUT];        // fp32 qkv_hidden
__device__ __nv_bfloat16 g_xh[(size_t)BT * D_MODEL];
__device__ __nv_bfloat16 g_xl[(size_t)BT * D_MODEL];
__device__ __nv_bfloat16 g_wqh[(size_t)D_MODEL * QKV_OUT];
__device__ __nv_bfloat16 g_wql[(size_t)D_MODEL * QKV_OUT];
__device__ __nv_bfloat16 g_wmh[(size_t)HIDDEN * D_MODEL];
__device__ __nv_bfloat16 g_wml[(size_t)HIDDEN * D_MODEL];
__device__ __nv_bfloat16 g_hh[(size_t)BT * HIDDEN];
__device__ __nv_bfloat16 g_hl[(size_t)BT * HIDDEN];

// ---------------- PTX helpers ----------------------------------------------
__device__ __forceinline__ uint32_t smem_u32(const void* p) {
    uint32_t a;
    asm("{ .reg .u64 t; cvta.to.shared.u64 t, %1; cvt.u32.u64 %0, t; }"
        : "=r"(a) : "l"(p));
    return a;
}
__device__ __forceinline__ void cp16(uint32_t dst, const void* src) {
    asm volatile("cp.async.cg.shared.global [%0], [%1], 16;" :: "r"(dst), "l"(src));
}
#define CP_COMMIT() asm volatile("cp.async.commit_group;")
#define CP_WAIT0()  asm volatile("cp.async.wait_group 0;")

__device__ __forceinline__ void ldsm_x4(uint32_t& r0, uint32_t& r1,
                                        uint32_t& r2, uint32_t& r3, uint32_t addr) {
    asm volatile("ldmatrix.sync.aligned.m8n8.x4.shared.b16 {%0,%1,%2,%3}, [%4];"
                 : "=r"(r0), "=r"(r1), "=r"(r2), "=r"(r3) : "r"(addr));
}
__device__ __forceinline__ void ldsm_x4t(uint32_t& r0, uint32_t& r1,
                                         uint32_t& r2, uint32_t& r3, uint32_t addr) {
    asm volatile("ldmatrix.sync.aligned.m8n8.x4.trans.shared.b16 {%0,%1,%2,%3}, [%4];"
                 : "=r"(r0), "=r"(r1), "=r"(r2), "=r"(r3) : "r"(addr));
}
__device__ __forceinline__ void mma_bf16(float* d,
                                         uint32_t a0, uint32_t a1, uint32_t a2, uint32_t a3,
                                         uint32_t b0, uint32_t b1) {
    asm volatile(
        "mma.sync.aligned.m16n8k16.row.col.f32.bf16.bf16.f32 "
        "{%0,%1,%2,%3}, {%4,%5,%6,%7}, {%8,%9}, {%0,%1,%2,%3};"
        : "+f"(d[0]), "+f"(d[1]), "+f"(d[2]), "+f"(d[3])
        : "r"(a0), "r"(a1), "r"(a2), "r"(a3), "r"(b0), "r"(b1));
}
__device__ __forceinline__ uint32_t pack_hi(float x, float y) {
    __nv_bfloat162 h = __float22bfloat162_rn(make_float2(x, y));
    return *(uint32_t*)&h;
}
__device__ __forceinline__ uint32_t pack_lo(float x, float y, uint32_t hi) {
    __nv_bfloat162 h = *(__nv_bfloat162*)&hi;
    __nv_bfloat162 l = __float22bfloat162_rn(make_float2(
        x - __bfloat162float(h.x), y - __bfloat162float(h.y)));
    return *(uint32_t*)&l;
}
__device__ __forceinline__ float warp_sum(float v) {
    #pragma unroll
    for (int o = 16; o > 0; o >>= 1) v += __shfl_xor_sync(0xffffffffu, v, o);
    return v;
}

// ---------------- 0) generic fp32 -> split bf16 -----------------------------
__global__ void split_kernel(const float* __restrict__ in,
                             __nv_bfloat16* __restrict__ oh,
                             __nv_bfloat16* __restrict__ ol) {
    int idx = blockIdx.x * blockDim.x + threadIdx.x;
    float4 v = ((const float4*)in)[idx];
    uint32_t h0 = pack_hi(v.x, v.y), h1 = pack_hi(v.z, v.w);
    uint32_t l0 = pack_lo(v.x, v.y, h0), l1 = pack_lo(v.z, v.w, h1);
    ((uint2*)oh)[idx] = make_uint2(h0, h1);
    ((uint2*)ol)[idx] = make_uint2(l0, l1);
}

// ---------------- 1) LayerNorm(inputs) -> split bf16 ------------------------
__global__ void ln_input_kernel(const float* __restrict__ in,
                                __nv_bfloat16* __restrict__ oh,
                                __nv_bfloat16* __restrict__ ol) {
    int row = blockIdx.x;
    const float4* src = (const float4*)(in + (size_t)row * D_MODEL);

    float4 v[2];
    float s = 0.f, sq = 0.f;
    #pragma unroll
    for (int i = 0; i < 2; i++) {
        v[i] = src[threadIdx.x + i * 256];
        s  += v[i].x + v[i].y + v[i].z + v[i].w;
        sq += v[i].x * v[i].x + v[i].y * v[i].y + v[i].z * v[i].z + v[i].w * v[i].w;
    }
    __shared__ float sh_s[8], sh_q[8];
    int lane = threadIdx.x & 31, wid = threadIdx.x >> 5;
    s = warp_sum(s); sq = warp_sum(sq);
    if (lane == 0) { sh_s[wid] = s; sh_q[wid] = sq; }
    __syncthreads();
    if (wid == 0) {
        float a = (lane < 8) ? sh_s[lane] : 0.f;
        float b = (lane < 8) ? sh_q[lane] : 0.f;
        a = warp_sum(a); b = warp_sum(b);
        if (lane == 0) { sh_s[0] = a; sh_q[0] = b; }
    }
    __syncthreads();
    float mean = sh_s[0] * (1.f / D_MODEL);
    float var  = sh_q[0] * (1.f / D_MODEL) - mean * mean;
    float r    = rsqrtf(var + 1e-5f);
    #pragma unroll
    for (int i = 0; i < 2; i++) {
        float a = (v[i].x - mean) * r, b = (v[i].y - mean) * r;
        float c = (v[i].z - mean) * r, d = (v[i].w - mean) * r;
        uint32_t h0 = pack_hi(a, b), h1 = pack_hi(c, d);
        uint32_t l0 = pack_lo(a, b, h0), l1 = pack_lo(c, d, h1);
        size_t o = (size_t)row * (D_MODEL / 4) + threadIdx.x + i * 256;
        ((uint2*)oh)[o] = make_uint2(h0, h1);
        ((uint2*)ol)[o] = make_uint2(l0, l1);
    }
}

// ============================================================================
// 2) cp.async double-buffered split-bf16 tensor GEMM
//    C[M,N] = A[M,K] @ W[K,N] + bias (+ res). CTA 128x128, kstage=32.
// ============================================================================
#define GSTAGE 32768

template<bool ADD_RES>
__global__ __launch_bounds__(256, 2)
void tc_gemm2(const __nv_bfloat16* __restrict__ Ah, const __nv_bfloat16* __restrict__ Al,
              int lda,
              const __nv_bfloat16* __restrict__ Bh, const __nv_bfloat16* __restrict__ Bl,
              int ldb,
              float* __restrict__ C, int ldc,
              const float* __restrict__ bias,
              const float* __restrict__ res,
              int K) {
    extern __shared__ char gsm[];
    const uint32_t smb = smem_u32(gsm);

    const int tid = threadIdx.x;
    const int l = tid & 31, w = tid >> 5;
    const int wm = (w & 3) * 32;
    const int wn = (w >> 2) * 64;
    const int bm = blockIdx.x * 128, bn = blockIdx.y * 128;

    // loader mapping
    const int ar = tid >> 1;
    const int ac0 = (tid & 1) * 2;
    const int br = tid >> 3;
    const int bc0 = (tid & 7) * 2;

    float acc[2][8][4];
    #pragma unroll
    for (int mt = 0; mt < 2; mt++)
        #pragma unroll
        for (int nt = 0; nt < 8; nt++)
            #pragma unroll
            for (int e = 0; e < 4; e++) acc[mt][nt][e] = 0.f;

    const int nkb = K / 32;

    auto issue = [&](int stage, int k0) {
        uint32_t sb = smb + stage * GSTAGE;
        #pragma unroll
        for (int j = 0; j < 2; j++) {
            int c = ac0 + j;
            uint32_t dst = sb + ar * 64 + 16 * (c ^ ((ar >> 1) & 3));
            const __nv_bfloat16* sh = Ah + (size_t)(bm + ar) * lda + k0 + c * 8;
            const __nv_bfloat16* sl = Al + (size_t)(bm + ar) * lda + k0 + c * 8;
            cp16(dst, sh);
            cp16(dst + 8192, sl);
        }
        #pragma unroll
        for (int j = 0; j < 2; j++) {
            int c = bc0 + j;
            uint32_t dst = sb + 16384 + br * 256 + 16 * ((c & 8) | ((c ^ br) & 7));
            const __nv_bfloat16* sh = Bh + (size_t)(k0 + br) * ldb + bn + c * 8;
            const __nv_bfloat16* sl = Bl + (size_t)(k0 + br) * ldb + bn + c * 8;
            cp16(dst, sh);
            cp16(dst + 8192, sl);
        }
    };

    issue(0, 0);
    CP_COMMIT();

    for (int kb = 0; kb < nkb; kb++) {
        CP_WAIT0();
        __syncthreads();
        if (kb + 1 < nkb) { issue((kb + 1) & 1, (kb + 1) * 32); CP_COMMIT(); }

        uint32_t sb = smb + (kb & 1) * GSTAGE;
        #pragma unroll
        for (int ks = 0; ks < 2; ks++) {
            uint32_t ah_[2][4], al_[2][4];
            #pragma unroll
            for (int mt = 0; mt < 2; mt++) {
                int r = wm + mt * 16 + (l & 15);
                int c = ks * 2 + (l >> 4);
                uint32_t off = sb + r * 64 + 16 * (c ^ ((r >> 1) & 3));
                ldsm_x4(ah_[mt][0], ah_[mt][1], ah_[mt][2], ah_[mt][3], off);
                ldsm_x4(al_[mt][0], al_[mt][1], al_[mt][2], al_[mt][3], off + 8192);
            }
            #pragma unroll
            for (int p = 0; p < 4; p++) {
                int g = (w >> 2) * 4 + p;
                int kk = ks * 16 + (l & 7) + ((l >> 3) & 1) * 8;
                int c = 2 * g + ((l >> 4) & 1);
                uint32_t off = sb + 16384 + kk * 256 + 16 * ((c & 8) | ((c ^ kk) & 7));
                uint32_t bh0, bh1, bh2, bh3, bl0, bl1, bl2, bl3;
                ldsm_x4t(bh0, bh1, bh2, bh3, off);
                ldsm_x4t(bl0, bl1, bl2, bl3, off + 8192);
                #pragma unroll
                for (int mt = 0; mt < 2; mt++) {
                    mma_bf16(acc[mt][p * 2],     ah_[mt][0], ah_[mt][1], ah_[mt][2], ah_[mt][3], bh0, bh1);
                    mma_bf16(acc[mt][p * 2],     ah_[mt][0], ah_[mt][1], ah_[mt][2], ah_[mt][3], bl0, bl1);
                    mma_bf16(acc[mt][p * 2],     al_[mt][0], al_[mt][1], al_[mt][2], al_[mt][3], bh0, bh1);
                    mma_bf16(acc[mt][p * 2 + 1], ah_[mt][0], ah_[mt][1], ah_[mt][2], ah_[mt][3], bh2, bh3);
                    mma_bf16(acc[mt][p * 2 + 1], ah_[mt][0], ah_[mt][1], ah_[mt][2], ah_[mt][3], bl2, bl3);
                    mma_bf16(acc[mt][p * 2 + 1], al_[mt][0], al_[mt][1], al_[mt][2], al_[mt][3], bh2, bh3);
                }
            }
        }
    }

    // epilogue
    #pragma unroll
    for (int mt = 0; mt < 2; mt++) {
        int row0 = bm + wm + mt * 16 + (l >> 2);
        #pragma unroll
        for (int nt = 0; nt < 8; nt++) {
            int col = bn + wn + nt * 8 + (l & 3) * 2;
            float b0 = bias[col], b1 = bias[col + 1];
            float* d = acc[mt][nt];
            float2 o0 = make_float2(d[0] + b0, d[1] + b1);
            float2 o1 = make_float2(d[2] + b0, d[3] + b1);
            if (ADD_RES) {
                float2 r0 = *(const float2*)(res + (size_t)row0 * ldc + col);
                float2 r1 = *(const float2*)(res + (size_t)(row0 + 8) * ldc + col);
                o0.x += r0.x; o0.y += r0.y;
                o1.x += r1.x; o1.y += r1.y;
            }
            *(float2*)(C + (size_t)row0 * ldc + col) = o0;
            *(float2*)(C + (size_t)(row0 + 8) * ldc + col) = o1;
        }
    }
}

// ---------------- 3a) per-head LN on q and k --------------------------------
__global__ void head_ln_kernel(float* __restrict__ qkv) {
    int gw   = (blockIdx.x * blockDim.x + threadIdx.x) >> 5;
    int lane = threadIdx.x & 31;
    int seg   = gw >> 16;
    int r     = gw & 65535;
    int token = r >> 4;
    int h     = r & 15;
    float* base = qkv + (size_t)token * QKV_OUT + seg * D_MODEL + h * HEAD;
    float4 v = ((float4*)base)[lane];
    float s = warp_sum(v.x + v.y + v.z + v.w) * (1.f / HEAD);
    float d0 = v.x - s, d1 = v.y - s, d2 = v.z - s, d3 = v.w - s;
    float var = warp_sum(d0 * d0 + d1 * d1 + d2 * d2 + d3 * d3) * (1.f / HEAD);
    float rr = rsqrtf(var + 1e-5f);
    ((float4*)base)[lane] = make_float4(d0 * rr, d1 * rr, d2 * rr, d3 * rr);
}

// ---------------- 3b) exact GELU -> split bf16 ------------------------------
__global__ void gelu_kernel(const float* __restrict__ qkv,
                            __nv_bfloat16* __restrict__ oh,
                            __nv_bfloat16* __restrict__ ol) {
    int idx = blockIdx.x * blockDim.x + threadIdx.x;
    int row = idx >> 11;
    int c4  = idx & 2047;
    float4 v = *((const float4*)(qkv + (size_t)row * QKV_OUT + 3 * D_MODEL) + c4);
    const float k = 0.70710678118654752f;
    v.x = 0.5f * v.x * (1.f + erff(v.x * k));
    v.y = 0.5f * v.y * (1.f + erff(v.y * k));
    v.z = 0.5f * v.z * (1.f + erff(v.z * k));
    v.w = 0.5f * v.w * (1.f + erff(v.w * k));
    uint32_t h0 = pack_hi(v.x, v.y), h1 = pack_hi(v.z, v.w);
    uint32_t l0 = pack_lo(v.x, v.y, h0), l1 = pack_lo(v.z, v.w, h1);
    size_t o = (size_t)row * (HIDDEN / 4) + c4;
    ((uint2*)oh)[o] = make_uint2(h0, h1);
    ((uint2*)ol)[o] = make_uint2(l0, l1);
}

// ============================================================================
// 4) tensor-core causal flash attention (split-bf16), adds into out
//    CTA: 128 q rows x full K sweep; 8 warps x 16 rows.
// ============================================================================
#define OFF_QH 0
#define OFF_QL 32768
#define OFF_KH 65536
#define OFF_KL 98304
#define OFF_VH 131072
#define OFF_VL 163840
#define FLASH_SMEM 196608

__device__ __forceinline__ void load_tile_split(const float* __restrict__ gbase,
                                                char* smh, char* sml, int tid) {
    int row = tid >> 1, half = tid & 1;
    const float* src = gbase + (size_t)row * QKV_OUT + half * 64;
    #pragma unroll
    for (int j = 0; j < 8; j++) {
        float4 f0 = *(const float4*)(src + j * 8);
        float4 f1 = *(const float4*)(src + j * 8 + 4);
        uint4 H, L;
        H.x = pack_hi(f0.x, f0.y); L.x = pack_lo(f0.x, f0.y, H.x);
        H.y = pack_hi(f0.z, f0.w); L.y = pack_lo(f0.z, f0.w, H.y);
        H.z = pack_hi(f1.x, f1.y); L.z = pack_lo(f1.x, f1.y, H.z);
        H.w = pack_hi(f1.z, f1.w); L.w = pack_lo(f1.z, f1.w, H.w);
        int c = half * 8 + j;
        int off = row * 256 + 16 * ((c & 8) | ((c ^ row) & 7));
        *(uint4*)(smh + off) = H;
        *(uint4*)(sml + off) = L;
    }
}

__global__ __launch_bounds__(256, 1)
void flash2_kernel(const float* __restrict__ qkv, float* __restrict__ out) {
    extern __shared__ char fsm[];
    const uint32_t sb = smem_u32(fsm);
    const int tid = threadIdx.x;
    const int l = tid & 31, w = tid >> 5;
    const int qt = (int)gridDim.x - 1 - (int)blockIdx.x;
    const int bh = blockIdx.y;
    const int b = bh >> 4, h = bh & 15;

    const float* qbase = qkv + (size_t)b * TT * QKV_OUT + h * HEAD;
    const float* kbase = qbase + D_MODEL;
    const float* vbase = qbase + 2 * D_MODEL;

    load_tile_split(qbase + (size_t)qt * 128 * QKV_OUT, fsm + OFF_QH, fsm + OFF_QL, tid);

    float O_[16][4];
    #pragma unroll
    for (int t = 0; t < 16; t++)
        #pragma unroll
        for (int e = 0; e < 4; e++) O_[t][e] = 0.f;
    float M0 = -INFINITY, M1 = -INFINITY, L0 = 0.f, L1 = 0.f;

    const float scale = 0.08838834764831845f;   // 1/sqrt(128)

    for (int kt = 0; kt <= qt; kt++) {
        __syncthreads();
        load_tile_split(kbase + (size_t)kt * 128 * QKV_OUT, fsm + OFF_KH, fsm + OFF_KL, tid);
        load_tile_split(vbase + (size_t)kt * 128 * QKV_OUT, fsm + OFF_VH, fsm + OFF_VL, tid);
        __syncthreads();

        // ---- S = Q K^T (per warp: 16 rows x 128 cols) ----
        float s_[16][4];
        #pragma unroll
        for (int t = 0; t < 16; t++)
            #pragma unroll
            for (int e = 0; e < 4; e++) s_[t][e] = 0.f;

        #pragma unroll
        for (int ks = 0; ks < 8; ks++) {
            int qr = w * 16 + (l & 15);
            int qc = ks * 2 + (l >> 4);
            uint32_t qoff = sb + OFF_QH + qr * 256 + 16 * ((qc & 8) | ((qc ^ qr) & 7));
            uint32_t qh0, qh1, qh2, qh3, ql0, ql1, ql2, ql3;
            ldsm_x4(qh0, qh1, qh2, qh3, qoff);
            ldsm_x4(ql0, ql1, ql2, ql3, qoff + 32768);
            #pragma unroll
            for (int g = 0; g < 8; g++) {
                int kr = g * 16 + (l & 7) + ((l >> 4) & 1) * 8;
                int kc = ks * 2 + ((l >> 3) & 1);
                uint32_t koff = sb + OFF_KH + kr * 256 + 16 * ((kc & 8) | ((kc ^ kr) & 7));
                uint32_t bh0, bh1, bh2, bh3, bl0, bl1, bl2, bl3;
                ldsm_x4(bh0, bh1, bh2, bh3, koff);
                ldsm_x4(bl0, bl1, bl2, bl3, koff + 32768);
                mma_bf16(s_[2 * g],     qh0, qh1, qh2, qh3, bh0, bh1);
                mma_bf16(s_[2 * g],     qh0, qh1, qh2, qh3, bl0, bl1);
                mma_bf16(s_[2 * g],     ql0, ql1, ql2, ql3, bh0, bh1);
                mma_bf16(s_[2 * g + 1], qh0, qh1, qh2, qh3, bh2, bh3);
                mma_bf16(s_[2 * g + 1], qh0, qh1, qh2, qh3, bl2, bl3);
                mma_bf16(s_[2 * g + 1], ql0, ql1, ql2, ql3, bh2, bh3);
            }
        }

        // ---- scale + causal mask ----
        #pragma unroll
        for (int t = 0; t < 16; t++)
            #pragma unroll
            for (int e = 0; e < 4; e++) s_[t][e] *= scale;

        if (kt == qt) {
            int qr0 = w * 16 + (l >> 2);
            int qr1 = qr0 + 8;
            #pragma unroll
            for (int t = 0; t < 16; t++) {
                int kc = t * 8 + (l & 3) * 2;
                if (kc     > qr0) s_[t][0] = -INFINITY;
                if (kc + 1 > qr0) s_[t][1] = -INFINITY;
                if (kc     > qr1) s_[t][2] = -INFINITY;
                if (kc + 1 > qr1) s_[t][3] = -INFINITY;
            }
        }

        // ---- online softmax (rows owned by 4-lane groups) ----
        float m0 = -INFINITY, m1 = -INFINITY;
        #pragma unroll
        for (int t = 0; t < 16; t++) {
            m0 = fmaxf(m0, fmaxf(s_[t][0], s_[t][1]));
            m1 = fmaxf(m1, fmaxf(s_[t][2], s_[t][3]));
        }
        #pragma unroll
        for (int o = 1; o < 4; o <<= 1) {
            m0 = fmaxf(m0, __shfl_xor_sync(0xffffffffu, m0, o));
            m1 = fmaxf(m1, __shfl_xor_sync(0xffffffffu, m1, o));
        }
        float nm0 = fmaxf(M0, m0), nm1 = fmaxf(M1, m1);
        float corr0 = __expf(M0 - nm0), corr1 = __expf(M1 - nm1);
        M0 = nm0; M1 = nm1;

        float ps0 = 0.f, ps1 = 0.f;
        #pragma unroll
        for (int t = 0; t < 16; t++) {
            s_[t][0] = __expf(s_[t][0] - nm0); ps0 += s_[t][0];
            s_[t][1] = __expf(s_[t][1] - nm0); ps0 += s_[t][1];
            s_[t][2] = __expf(s_[t][2] - nm1); ps1 += s_[t][2];
            s_[t][3] = __expf(s_[t][3] - nm1); ps1 += s_[t][3];
        }
        #pragma unroll
        for (int o = 1; o < 4; o <<= 1) {
            ps0 += __shfl_xor_sync(0xffffffffu, ps0, o);
            ps1 += __shfl_xor_sync(0xffffffffu, ps1, o);
        }
        L0 = L0 * corr0 + ps0;
        L1 = L1 * corr1 + ps1;
        #pragma unroll
        for (int t = 0; t < 16; t++) {
            O_[t][0] *= corr0; O_[t][1] *= corr0;
            O_[t][2] *= corr1; O_[t][3] *= corr1;
        }

        // ---- O += P V ----
        #pragma unroll
        for (int s8 = 0; s8 < 8; s8++) {
            float* t0 = s_[2 * s8];
            float* t1 = s_[2 * s8 + 1];
            uint32_t ph[4], pl[4];
            ph[0] = pack_hi(t0[0], t0[1]); pl[0] = pack_lo(t0[0], t0[1], ph[0]);
            ph[1] = pack_hi(t0[2], t0[3]); pl[1] = pack_lo(t0[2], t0[3], ph[1]);
            ph[2] = pack_hi(t1[0], t1[1]); pl[2] = pack_lo(t1[0], t1[1], ph[2]);
            ph[3] = pack_hi(t1[2], t1[3]); pl[3] = pack_lo(t1[2], t1[3], ph[3]);
            #pragma unroll
            for (int g = 0; g < 8; g++) {
                int vr = s8 * 16 + (l & 7) + ((l >> 3) & 1) * 8;
                int vc = 2 * g + ((l >> 4) & 1);
                uint32_t voff = sb + OFF_VH + vr * 256 + 16 * ((vc & 8) | ((vc ^ vr) & 7));
                uint32_t vh0, vh1, vh2, vh3, vl0, vl1, vl2, vl3;
                ldsm_x4t(vh0, vh1, vh2, vh3, voff);
                ldsm_x4t(vl0, vl1, vl2, vl3, voff + 32768);
                mma_bf16(O_[2 * g],     ph[0], ph[1], ph[2], ph[3], vh0, vh1);
                mma_bf16(O_[2 * g],     ph[0], ph[1], ph[2], ph[3], vl0, vl1);
                mma_bf16(O_[2 * g],     pl[0], pl[1], pl[2], pl[3], vh0, vh1);
                mma_bf16(O_[2 * g + 1], ph[0], ph[1], ph[2], ph[3], vh2, vh3);
                mma_bf16(O_[2 * g + 1], ph[0], ph[1], ph[2], ph[3], vl2, vl3);
                mma_bf16(O_[2 * g + 1], pl[0], pl[1], pl[2], pl[3], vh2, vh3);
            }
        }
    }

    // ---- epilogue: out += O / L ----
    float inv0 = 1.f / L0, inv1 = 1.f / L1;
    int token = qt * 128 + w * 16 + (l >> 2);
    float* row0p = out + (size_t)(b * TT + token) * D_MODEL + h * HEAD;
    float* row1p = row0p + (size_t)8 * D_MODEL;
    #pragma unroll
    for (int t = 0; t < 16; t++) {
        int col = t * 8 + (l & 3) * 2;
        float2 v0 = *(float2*)(row0p + col);
        v0.x += O_[t][0] * inv0; v0.y += O_[t][1] * inv0;
        *(float2*)(row0p + col) = v0;
        float2 v1 = *(float2*)(row1p + col);
        v1.x += O_[t][2] * inv1; v1.y += O_[t][3] * inv1;
        *(float2*)(row1p + col) = v1;
    }
}

// ---------------- launch ----------------------------------------------------
extern "C" void kernel_launch(void* const* d_in, const int* in_sizes, int n_in,
                              void* d_out, int out_size) {
    const float* inputs = (const float*)d_in[0];
    const float* W_qkv  = (const float*)d_in[1];
    const float* b_qkv  = (const float*)d_in[2];
    const float* W_mlp  = (const float*)d_in[3];
    const float* b_mlp  = (const float*)d_in[4];
    float* out = (float*)d_out;

    void *pq, *pxh, *pxl, *pwqh, *pwql, *pwmh, *pwml, *phh, *phl;
    cudaGetSymbolAddress(&pq,  g_qkv);
    cudaGetSymbolAddress(&pxh, g_xh);  cudaGetSymbolAddress(&pxl, g_xl);
    cudaGetSymbolAddress(&pwqh, g_wqh); cudaGetSymbolAddress(&pwql, g_wql);
    cudaGetSymbolAddress(&pwmh, g_wmh); cudaGetSymbolAddress(&pwml, g_wml);
    cudaGetSymbolAddress(&phh, g_hh);  cudaGetSymbolAddress(&phl, g_hl);
    float* gq = (float*)pq;

    cudaFuncSetAttribute(tc_gemm2<false>,
                         cudaFuncAttributeMaxDynamicSharedMemorySize, 2 * GSTAGE);
    cudaFuncSetAttribute(tc_gemm2<true>,
                         cudaFuncAttributeMaxDynamicSharedMemorySize, 2 * GSTAGE);
    cudaFuncSetAttribute(flash2_kernel,
                         cudaFuncAttributeMaxDynamicSharedMemorySize, FLASH_SMEM);

    // 0) split weights to bf16 hi/lo
    split_kernel<<<(D_MODEL * QKV_OUT / 4) / 256, 256>>>(
        W_qkv, (__nv_bfloat16*)pwqh, (__nv_bfloat16*)pwql);
    split_kernel<<<(HIDDEN * D_MODEL / 4) / 256, 256>>>(
        W_mlp, (__nv_bfloat16*)pwmh, (__nv_bfloat16*)pwml);

    // 1) LN(inputs) -> split bf16
    ln_input_kernel<<<BT, 256>>>(inputs, (__nv_bfloat16*)pxh, (__nv_bfloat16*)pxl);

    // 2) qkv_hidden = x @ W_qkv + b_qkv
    tc_gemm2<false><<<dim3(BT / 128, QKV_OUT / 128), 256, 2 * GSTAGE>>>(
        (__nv_bfloat16*)pxh, (__nv_bfloat16*)pxl, D_MODEL,
        (__nv_bfloat16*)pwqh, (__nv_bfloat16*)pwql, QKV_OUT,
        gq, QKV_OUT, b_qkv, nullptr, D_MODEL);

    // 3) head LN on q,k (in place) ; GELU(hidden) -> split bf16
    head_ln_kernel<<<(BT * NUM_HEADS * 2) / 8, 256>>>(gq);
    gelu_kernel<<<(BT * (HIDDEN / 4)) / 256, 256>>>(
        gq, (__nv_bfloat16*)phh, (__nv_bfloat16*)phl);

    // 4) out = gelu(hidden) @ W_mlp + b_mlp + inputs
    tc_gemm2<true><<<dim3(BT / 128, D_MODEL / 128), 256, 2 * GSTAGE>>>(
        (__nv_bfloat16*)phh, (__nv_bfloat16*)phl, HIDDEN,
        (__nv_bfloat16*)pwmh, (__nv_bfloat16*)pwml, D_MODEL,
        out, D_MODEL, b_mlp, inputs, HIDDEN);

    // 5) out += attention(q, k, v)
    flash2_kernel<<<dim3(TT / 128, BB * NUM_HEADS), 256, FLASH_SMEM>>>(gq, out);
}

// round 5
// speedup vs baseline: 3.2354x; 1.0581x over previous
#include <cuda_runtime.h>
#include <cuda_bf16.h>
#include <math.h>
#include <stdint.h>

#define D_MODEL   2048
#define NUM_HEADS 16
#define HEAD      128
#define FAN       4
#define QKV_OUT   (3 * D_MODEL + FAN * D_MODEL)   // 14336
#define HIDDEN    (FAN * D_MODEL)                 // 8192
#define BB        2
#define TT        2048
#define BT        (BB * TT)                       // 4096
#define QKV3      (3 * D_MODEL)                   // 6144

// ---------------- scratch (device globals) ---------------------------------
__device__ float         g_qkv[(size_t)BT * QKV3];           // fp32 q,k,v
__device__ __nv_bfloat16 g_xh[(size_t)BT * D_MODEL];
__device__ __nv_bfloat16 g_xl[(size_t)BT * D_MODEL];
__device__ __nv_bfloat16 g_wqh[(size_t)D_MODEL * QKV_OUT];
__device__ __nv_bfloat16 g_wql[(size_t)D_MODEL * QKV_OUT];
__device__ __nv_bfloat16 g_wmh[(size_t)HIDDEN * D_MODEL];
__device__ __nv_bfloat16 g_wml[(size_t)HIDDEN * D_MODEL];
__device__ __nv_bfloat16 g_hh[(size_t)BT * HIDDEN];
__device__ __nv_bfloat16 g_hl[(size_t)BT * HIDDEN];
// head-major [b][h][t][d] split q/k/v for flash
__device__ __nv_bfloat16 g_qh[(size_t)BT * D_MODEL];
__device__ __nv_bfloat16 g_ql[(size_t)BT * D_MODEL];
__device__ __nv_bfloat16 g_kh[(size_t)BT * D_MODEL];
__device__ __nv_bfloat16 g_kl[(size_t)BT * D_MODEL];
__device__ __nv_bfloat16 g_vh[(size_t)BT * D_MODEL];
__device__ __nv_bfloat16 g_vl[(size_t)BT * D_MODEL];

// ---------------- PTX helpers ----------------------------------------------
__device__ __forceinline__ uint32_t smem_u32(const void* p) {
    uint32_t a;
    asm("{ .reg .u64 t; cvta.to.shared.u64 t, %1; cvt.u32.u64 %0, t; }"
        : "=r"(a) : "l"(p));
    return a;
}
__device__ __forceinline__ void cp16(uint32_t dst, const void* src) {
    asm volatile("cp.async.cg.shared.global [%0], [%1], 16;" :: "r"(dst), "l"(src));
}
#define CP_COMMIT() asm volatile("cp.async.commit_group;")
#define CP_WAIT0()  asm volatile("cp.async.wait_group 0;")
#define CP_WAIT1()  asm volatile("cp.async.wait_group 1;")

__device__ __forceinline__ void ldsm_x4(uint32_t& r0, uint32_t& r1,
                                        uint32_t& r2, uint32_t& r3, uint32_t addr) {
    asm volatile("ldmatrix.sync.aligned.m8n8.x4.shared.b16 {%0,%1,%2,%3}, [%4];"
                 : "=r"(r0), "=r"(r1), "=r"(r2), "=r"(r3) : "r"(addr));
}
__device__ __forceinline__ void ldsm_x4t(uint32_t& r0, uint32_t& r1,
                                         uint32_t& r2, uint32_t& r3, uint32_t addr) {
    asm volatile("ldmatrix.sync.aligned.m8n8.x4.trans.shared.b16 {%0,%1,%2,%3}, [%4];"
                 : "=r"(r0), "=r"(r1), "=r"(r2), "=r"(r3) : "r"(addr));
}
__device__ __forceinline__ void mma_bf16(float* d,
                                         uint32_t a0, uint32_t a1, uint32_t a2, uint32_t a3,
                                         uint32_t b0, uint32_t b1) {
    asm volatile(
        "mma.sync.aligned.m16n8k16.row.col.f32.bf16.bf16.f32 "
        "{%0,%1,%2,%3}, {%4,%5,%6,%7}, {%8,%9}, {%0,%1,%2,%3};"
        : "+f"(d[0]), "+f"(d[1]), "+f"(d[2]), "+f"(d[3])
        : "r"(a0), "r"(a1), "r"(a2), "r"(a3), "r"(b0), "r"(b1));
}
__device__ __forceinline__ uint32_t pack_hi(float x, float y) {
    __nv_bfloat162 h = __float22bfloat162_rn(make_float2(x, y));
    return *(uint32_t*)&h;
}
__device__ __forceinline__ uint32_t pack_lo(float x, float y, uint32_t hi) {
    __nv_bfloat162 h = *(__nv_bfloat162*)&hi;
    __nv_bfloat162 l = __float22bfloat162_rn(make_float2(
        x - __bfloat162float(h.x), y - __bfloat162float(h.y)));
    return *(uint32_t*)&l;
}
__device__ __forceinline__ float warp_sum(float v) {
    #pragma unroll
    for (int o = 16; o > 0; o >>= 1) v += __shfl_xor_sync(0xffffffffu, v, o);
    return v;
}
__device__ __forceinline__ float gelu_f(float x) {
    return 0.5f * x * (1.f + erff(x * 0.70710678118654752f));
}

// ---------------- 0) fp32 -> split bf16 (weights) ---------------------------
__global__ void split_kernel(const float* __restrict__ in,
                             __nv_bfloat16* __restrict__ oh,
                             __nv_bfloat16* __restrict__ ol) {
    int idx = blockIdx.x * blockDim.x + threadIdx.x;
    float4 v = ((const float4*)in)[idx];
    uint32_t h0 = pack_hi(v.x, v.y), h1 = pack_hi(v.z, v.w);
    uint32_t l0 = pack_lo(v.x, v.y, h0), l1 = pack_lo(v.z, v.w, h1);
    ((uint2*)oh)[idx] = make_uint2(h0, h1);
    ((uint2*)ol)[idx] = make_uint2(l0, l1);
}

// ---------------- 1) LayerNorm(inputs) -> split bf16 ------------------------
__global__ void ln_input_kernel(const float* __restrict__ in,
                                __nv_bfloat16* __restrict__ oh,
                                __nv_bfloat16* __restrict__ ol) {
    int row = blockIdx.x;
    const float4* src = (const float4*)(in + (size_t)row * D_MODEL);

    float4 v[2];
    float s = 0.f, sq = 0.f;
    #pragma unroll
    for (int i = 0; i < 2; i++) {
        v[i] = src[threadIdx.x + i * 256];
        s  += v[i].x + v[i].y + v[i].z + v[i].w;
        sq += v[i].x * v[i].x + v[i].y * v[i].y + v[i].z * v[i].z + v[i].w * v[i].w;
    }
    __shared__ float sh_s[8], sh_q[8];
    int lane = threadIdx.x & 31, wid = threadIdx.x >> 5;
    s = warp_sum(s); sq = warp_sum(sq);
    if (lane == 0) { sh_s[wid] = s; sh_q[wid] = sq; }
    __syncthreads();
    if (wid == 0) {
        float a = (lane < 8) ? sh_s[lane] : 0.f;
        float b = (lane < 8) ? sh_q[lane] : 0.f;
        a = warp_sum(a); b = warp_sum(b);
        if (lane == 0) { sh_s[0] = a; sh_q[0] = b; }
    }
    __syncthreads();
    float mean = sh_s[0] * (1.f / D_MODEL);
    float var  = sh_q[0] * (1.f / D_MODEL) - mean * mean;
    float r    = rsqrtf(var + 1e-5f);
    #pragma unroll
    for (int i = 0; i < 2; i++) {
        float a = (v[i].x - mean) * r, b = (v[i].y - mean) * r;
        float c = (v[i].z - mean) * r, d = (v[i].w - mean) * r;
        uint32_t h0 = pack_hi(a, b), h1 = pack_hi(c, d);
        uint32_t l0 = pack_lo(a, b, h0), l1 = pack_lo(c, d, h1);
        size_t o = (size_t)row * (D_MODEL / 4) + threadIdx.x + i * 256;
        ((uint2*)oh)[o] = make_uint2(h0, h1);
        ((uint2*)ol)[o] = make_uint2(l0, l1);
    }
}

// ============================================================================
// 2) 3-stage cp.async split-bf16 tensor GEMM. CTA 128x128, kstage=32.
//    QKV mode: hidden column blocks get fused GELU + split-bf16 output.
// ============================================================================
#define GSTAGE 32768
#define GEMM_SMEM (3 * GSTAGE)

template<bool QKV, bool ADD_RES>
__global__ __launch_bounds__(256, 2)
void tc_gemm3(const __nv_bfloat16* __restrict__ Ah, const __nv_bfloat16* __restrict__ Al,
              int lda,
              const __nv_bfloat16* __restrict__ Bh, const __nv_bfloat16* __restrict__ Bl,
              int ldb,
              float* __restrict__ C, int ldc,
              const float* __restrict__ bias,
              const float* __restrict__ res,
              __nv_bfloat16* __restrict__ Hh, __nv_bfloat16* __restrict__ Hl,
              int K) {
    extern __shared__ char gsm[];
    const uint32_t smb = smem_u32(gsm);

    const int tid = threadIdx.x;
    const int l = tid & 31, w = tid >> 5;
    const int wm = (w & 3) * 32;
    const int wn = (w >> 2) * 64;
    const int bm = blockIdx.x * 128, bn = blockIdx.y * 128;

    const int ar = tid >> 1;
    const int ac0 = (tid & 1) * 2;
    const int br = tid >> 3;
    const int bc0 = (tid & 7) * 2;

    float acc[2][8][4];
    #pragma unroll
    for (int mt = 0; mt < 2; mt++)
        #pragma unroll
        for (int nt = 0; nt < 8; nt++)
            #pragma unroll
            for (int e = 0; e < 4; e++) acc[mt][nt][e] = 0.f;

    const int nkb = K / 32;

    auto issue = [&](int stage, int k0) {
        uint32_t sb = smb + stage * GSTAGE;
        #pragma unroll
        for (int j = 0; j < 2; j++) {
            int c = ac0 + j;
            uint32_t dst = sb + ar * 64 + 16 * (c ^ ((ar >> 1) & 3));
            cp16(dst,        Ah + (size_t)(bm + ar) * lda + k0 + c * 8);
            cp16(dst + 8192, Al + (size_t)(bm + ar) * lda + k0 + c * 8);
        }
        #pragma unroll
        for (int j = 0; j < 2; j++) {
            int c = bc0 + j;
            uint32_t dst = sb + 16384 + br * 256 + 16 * ((c & 8) | ((c ^ br) & 7));
            cp16(dst,        Bh + (size_t)(k0 + br) * ldb + bn + c * 8);
            cp16(dst + 8192, Bl + (size_t)(k0 + br) * ldb + bn + c * 8);
        }
    };

    issue(0, 0);  CP_COMMIT();
    issue(1, 32); CP_COMMIT();

    int cur = 0, iss = 2;
    for (int kb = 0; kb < nkb; kb++) {
        if (kb + 1 < nkb) { CP_WAIT1(); } else { CP_WAIT0(); }
        __syncthreads();
        if (kb + 2 < nkb) { issue(iss, (kb + 2) * 32); CP_COMMIT(); }

        uint32_t sb = smb + cur * GSTAGE;
        #pragma unroll
        for (int ks = 0; ks < 2; ks++) {
            uint32_t ah_[2][4], al_[2][4];
            #pragma unroll
            for (int mt = 0; mt < 2; mt++) {
                int r = wm + mt * 16 + (l & 15);
                int c = ks * 2 + (l >> 4);
                uint32_t off = sb + r * 64 + 16 * (c ^ ((r >> 1) & 3));
                ldsm_x4(ah_[mt][0], ah_[mt][1], ah_[mt][2], ah_[mt][3], off);
                ldsm_x4(al_[mt][0], al_[mt][1], al_[mt][2], al_[mt][3], off + 8192);
            }
            #pragma unroll
            for (int p = 0; p < 4; p++) {
                int g = (w >> 2) * 4 + p;
                int kk = ks * 16 + (l & 7) + ((l >> 3) & 1) * 8;
                int c = 2 * g + ((l >> 4) & 1);
                uint32_t off = sb + 16384 + kk * 256 + 16 * ((c & 8) | ((c ^ kk) & 7));
                uint32_t bh0, bh1, bh2, bh3, bl0, bl1, bl2, bl3;
                ldsm_x4t(bh0, bh1, bh2, bh3, off);
                ldsm_x4t(bl0, bl1, bl2, bl3, off + 8192);
                #pragma unroll
                for (int mt = 0; mt < 2; mt++) {
                    mma_bf16(acc[mt][p * 2],     ah_[mt][0], ah_[mt][1], ah_[mt][2], ah_[mt][3], bh0, bh1);
                    mma_bf16(acc[mt][p * 2],     ah_[mt][0], ah_[mt][1], ah_[mt][2], ah_[mt][3], bl0, bl1);
                    mma_bf16(acc[mt][p * 2],     al_[mt][0], al_[mt][1], al_[mt][2], al_[mt][3], bh0, bh1);
                    mma_bf16(acc[mt][p * 2 + 1], ah_[mt][0], ah_[mt][1], ah_[mt][2], ah_[mt][3], bh2, bh3);
                    mma_bf16(acc[mt][p * 2 + 1], ah_[mt][0], ah_[mt][1], ah_[mt][2], ah_[mt][3], bl2, bl3);
                    mma_bf16(acc[mt][p * 2 + 1], al_[mt][0], al_[mt][1], al_[mt][2], al_[mt][3], bh2, bh3);
                }
            }
        }
        cur = (cur + 1 == 3) ? 0 : cur + 1;
        iss = (iss + 1 == 3) ? 0 : iss + 1;
    }

    // ---- epilogue ----
    if (QKV && bn >= QKV3) {
        // hidden block: fused GELU + split bf16
        #pragma unroll
        for (int mt = 0; mt < 2; mt++) {
            int row0 = bm + wm + mt * 16 + (l >> 2);
            #pragma unroll
            for (int nt = 0; nt < 8; nt++) {
                int col = bn + wn + nt * 8 + (l & 3) * 2;
                int hcol = col - QKV3;
                float b0 = bias[col], b1 = bias[col + 1];
                float* d = acc[mt][nt];
                float a0 = gelu_f(d[0] + b0), a1 = gelu_f(d[1] + b1);
                float a2 = gelu_f(d[2] + b0), a3 = gelu_f(d[3] + b1);
                uint32_t h0 = pack_hi(a0, a1), lo0 = pack_lo(a0, a1, h0);
                uint32_t h1 = pack_hi(a2, a3), lo1 = pack_lo(a2, a3, h1);
                *(uint32_t*)(Hh + (size_t)row0 * HIDDEN + hcol) = h0;
                *(uint32_t*)(Hl + (size_t)row0 * HIDDEN + hcol) = lo0;
                *(uint32_t*)(Hh + (size_t)(row0 + 8) * HIDDEN + hcol) = h1;
                *(uint32_t*)(Hl + (size_t)(row0 + 8) * HIDDEN + hcol) = lo1;
            }
        }
    } else {
        #pragma unroll
        for (int mt = 0; mt < 2; mt++) {
            int row0 = bm + wm + mt * 16 + (l >> 2);
            #pragma unroll
            for (int nt = 0; nt < 8; nt++) {
                int col = bn + wn + nt * 8 + (l & 3) * 2;
                float b0 = bias[col], b1 = bias[col + 1];
                float* d = acc[mt][nt];
                float2 o0 = make_float2(d[0] + b0, d[1] + b1);
                float2 o1 = make_float2(d[2] + b0, d[3] + b1);
                if (ADD_RES) {
                    float2 r0 = *(const float2*)(res + (size_t)row0 * ldc + col);
                    float2 r1 = *(const float2*)(res + (size_t)(row0 + 8) * ldc + col);
                    o0.x += r0.x; o0.y += r0.y;
                    o1.x += r1.x; o1.y += r1.y;
                }
                *(float2*)(C + (size_t)row0 * ldc + col) = o0;
                *(float2*)(C + (size_t)(row0 + 8) * ldc + col) = o1;
            }
        }
    }
}

// ---------------- 3) q,k head-LN + split; v split (head-major out) ----------
__global__ void qkv_post_kernel(const float* __restrict__ qkv,
                                __nv_bfloat16* __restrict__ qh, __nv_bfloat16* __restrict__ ql,
                                __nv_bfloat16* __restrict__ kh, __nv_bfloat16* __restrict__ kl,
                                __nv_bfloat16* __restrict__ vh, __nv_bfloat16* __restrict__ vl) {
    int gw   = (blockIdx.x * blockDim.x + threadIdx.x) >> 5;  // 0..196607
    int lane = threadIdx.x & 31;
    int seg   = gw >> 16;        // 0=q, 1=k, 2=v
    int r     = gw & 65535;
    int token = r >> 4;
    int h     = r & 15;
    const float* base = qkv + (size_t)token * QKV3 + seg * D_MODEL + h * HEAD;
    float4 v = ((const float4*)base)[lane];
    if (seg < 2) {
        float s = warp_sum(v.x + v.y + v.z + v.w) * (1.f / HEAD);
        float d0 = v.x - s, d1 = v.y - s, d2 = v.z - s, d3 = v.w - s;
        float var = warp_sum(d0 * d0 + d1 * d1 + d2 * d2 + d3 * d3) * (1.f / HEAD);
        float rr = rsqrtf(var + 1e-5f);
        v = make_float4(d0 * rr, d1 * rr, d2 * rr, d3 * rr);
    }
    int b = token >> 11, tt = token & 2047;
    size_t o = ((((size_t)b * 16 + h) * 2048 + tt) * 128 + lane * 4) >> 2; // uint2 idx
    uint32_t h0 = pack_hi(v.x, v.y), h1 = pack_hi(v.z, v.w);
    uint32_t l0 = pack_lo(v.x, v.y, h0), l1 = pack_lo(v.z, v.w, h1);
    __nv_bfloat16* oh = (seg == 0) ? qh : (seg == 1) ? kh : vh;
    __nv_bfloat16* ol = (seg == 0) ? ql : (seg == 1) ? kl : vl;
    ((uint2*)oh)[o] = make_uint2(h0, h1);
    ((uint2*)ol)[o] = make_uint2(l0, l1);
}

// ============================================================================
// 4) flash v3: presplit head-major q/k/v, BK=64 K/V double-buffered cp.async
// ============================================================================
#define FLASH_SMEM 196608   // Q hi/lo 64KB + 2 stages x (K,V hi/lo) 64KB

__global__ __launch_bounds__(256, 1)
void flash3_kernel(const __nv_bfloat16* __restrict__ qh, const __nv_bfloat16* __restrict__ ql,
                   const __nv_bfloat16* __restrict__ kh, const __nv_bfloat16* __restrict__ kl,
                   const __nv_bfloat16* __restrict__ vh, const __nv_bfloat16* __restrict__ vl,
                   float* __restrict__ out) {
    extern __shared__ char fsm[];
    const uint32_t sb = smem_u32(fsm);
    const int tid = threadIdx.x;
    const int l = tid & 31, w = tid >> 5;
    const int qt = (int)gridDim.x - 1 - (int)blockIdx.x;   // 0..15
    const int bh = blockIdx.y;                              // b*16 + h
    const size_t hbase = (size_t)bh * 2048 * 128;

    // ---- issue Q (128 rows x 256B, hi+lo) ----
    {
        int row = tid >> 1, half = tid & 1;
        const __nv_bfloat16* sq = qh + hbase + (size_t)(qt * 128 + row) * 128;
        const __nv_bfloat16* sl = ql + hbase + (size_t)(qt * 128 + row) * 128;
        #pragma unroll
        for (int j = 0; j < 8; j++) {
            int c = half * 8 + j;
            uint32_t dst = sb + row * 256 + 16 * ((c & 8) | ((c ^ row) & 7));
            cp16(dst,         sq + c * 8);
            cp16(dst + 32768, sl + c * 8);
        }
    }
    // ---- issue K/V stage loader ----
    auto issue_kv = [&](int stage, int kt) {
        uint32_t stb = sb + 65536 + stage * 65536;
        int r = tid >> 2, q4 = tid & 3;
        const __nv_bfloat16* pkh = kh + hbase + (size_t)(kt * 64 + r) * 128;
        const __nv_bfloat16* pkl = kl + hbase + (size_t)(kt * 64 + r) * 128;
        const __nv_bfloat16* pvh = vh + hbase + (size_t)(kt * 64 + r) * 128;
        const __nv_bfloat16* pvl = vl + hbase + (size_t)(kt * 64 + r) * 128;
        #pragma unroll
        for (int j = 0; j < 4; j++) {
            int c = q4 * 4 + j;
            uint32_t sw = r * 256 + 16 * ((c & 8) | ((c ^ r) & 7));
            cp16(stb + sw,         pkh + c * 8);
            cp16(stb + 16384 + sw, pkl + c * 8);
            cp16(stb + 32768 + sw, pvh + c * 8);
            cp16(stb + 49152 + sw, pvl + c * 8);
        }
    };
    issue_kv(0, 0);
    CP_COMMIT();

    float O_[16][4];
    #pragma unroll
    for (int t = 0; t < 16; t++)
        #pragma unroll
        for (int e = 0; e < 4; e++) O_[t][e] = 0.f;
    float M0 = -INFINITY, M1 = -INFINITY, L0 = 0.f, L1 = 0.f;
    const float scale = 0.08838834764831845f;   // 1/sqrt(128)
    const int ktmax = 2 * qt + 1;

    for (int kt = 0; kt <= ktmax; kt++) {
        CP_WAIT0();
        __syncthreads();
        if (kt < ktmax) { issue_kv((kt + 1) & 1, kt + 1); CP_COMMIT(); }

        uint32_t stb = sb + 65536 + (kt & 1) * 65536;

        // ---- S = Q K^T (16 q-rows x 64 k-cols per warp) ----
        float s_[8][4];
        #pragma unroll
        for (int t = 0; t < 8; t++)
            #pragma unroll
            for (int e = 0; e < 4; e++) s_[t][e] = 0.f;

        #pragma unroll
        for (int ks = 0; ks < 8; ks++) {
            int qr = w * 16 + (l & 15);
            int qc = ks * 2 + (l >> 4);
            uint32_t qoff = sb + qr * 256 + 16 * ((qc & 8) | ((qc ^ qr) & 7));
            uint32_t qh0, qh1, qh2, qh3, ql0, ql1, ql2, ql3;
            ldsm_x4(qh0, qh1, qh2, qh3, qoff);
            ldsm_x4(ql0, ql1, ql2, ql3, qoff + 32768);
            #pragma unroll
            for (int g = 0; g < 4; g++) {
                int kr = g * 16 + (l & 7) + ((l >> 4) & 1) * 8;
                int kc = ks * 2 + ((l >> 3) & 1);
                uint32_t koff = stb + kr * 256 + 16 * ((kc & 8) | ((kc ^ kr) & 7));
                uint32_t bh0, bh1, bh2, bh3, bl0, bl1, bl2, bl3;
                ldsm_x4(bh0, bh1, bh2, bh3, koff);
                ldsm_x4(bl0, bl1, bl2, bl3, koff + 16384);
                mma_bf16(s_[2 * g],     qh0, qh1, qh2, qh3, bh0, bh1);
                mma_bf16(s_[2 * g],     qh0, qh1, qh2, qh3, bl0, bl1);
                mma_bf16(s_[2 * g],     ql0, ql1, ql2, ql3, bh0, bh1);
                mma_bf16(s_[2 * g + 1], qh0, qh1, qh2, qh3, bh2, bh3);
                mma_bf16(s_[2 * g + 1], qh0, qh1, qh2, qh3, bl2, bl3);
                mma_bf16(s_[2 * g + 1], ql0, ql1, ql2, ql3, bh2, bh3);
            }
        }

        #pragma unroll
        for (int t = 0; t < 8; t++)
            #pragma unroll
            for (int e = 0; e < 4; e++) s_[t][e] *= scale;

        if (kt >= 2 * qt) {           // diagonal region: element mask
            int qr0 = qt * 128 + w * 16 + (l >> 2);
            int qr1 = qr0 + 8;
            #pragma unroll
            for (int t = 0; t < 8; t++) {
                int kc = kt * 64 + t * 8 + (l & 3) * 2;
                if (kc     > qr0) s_[t][0] = -INFINITY;
                if (kc + 1 > qr0) s_[t][1] = -INFINITY;
                if (kc     > qr1) s_[t][2] = -INFINITY;
                if (kc + 1 > qr1) s_[t][3] = -INFINITY;
            }
        }

        // ---- online softmax (rows owned by 4-lane groups) ----
        float m0 = -INFINITY, m1 = -INFINITY;
        #pragma unroll
        for (int t = 0; t < 8; t++) {
            m0 = fmaxf(m0, fmaxf(s_[t][0], s_[t][1]));
            m1 = fmaxf(m1, fmaxf(s_[t][2], s_[t][3]));
        }
        #pragma unroll
        for (int o = 1; o < 4; o <<= 1) {
            m0 = fmaxf(m0, __shfl_xor_sync(0xffffffffu, m0, o));
            m1 = fmaxf(m1, __shfl_xor_sync(0xffffffffu, m1, o));
        }
        float nm0 = fmaxf(M0, m0), nm1 = fmaxf(M1, m1);
        float corr0 = __expf(M0 - nm0), corr1 = __expf(M1 - nm1);
        M0 = nm0; M1 = nm1;

        float ps0 = 0.f, ps1 = 0.f;
        #pragma unroll
        for (int t = 0; t < 8; t++) {
            s_[t][0] = __expf(s_[t][0] - nm0); ps0 += s_[t][0];
            s_[t][1] = __expf(s_[t][1] - nm0); ps0 += s_[t][1];
            s_[t][2] = __expf(s_[t][2] - nm1); ps1 += s_[t][2];
            s_[t][3] = __expf(s_[t][3] - nm1); ps1 += s_[t][3];
        }
        #pragma unroll
        for (int o = 1; o < 4; o <<= 1) {
            ps0 += __shfl_xor_sync(0xffffffffu, ps0, o);
            ps1 += __shfl_xor_sync(0xffffffffu, ps1, o);
        }
        L0 = L0 * corr0 + ps0;
        L1 = L1 * corr1 + ps1;
        #pragma unroll
        for (int t = 0; t < 8; t++) {
            O_[2 * t][0]     *= corr0; O_[2 * t][1]     *= corr0;
            O_[2 * t][2]     *= corr1; O_[2 * t][3]     *= corr1;
            O_[2 * t + 1][0] *= corr0; O_[2 * t + 1][1] *= corr0;
            O_[2 * t + 1][2] *= corr1; O_[2 * t + 1][3] *= corr1;
        }

        // ---- O += P V ----
        #pragma unroll
        for (int s8 = 0; s8 < 4; s8++) {
            float* t0 = s_[2 * s8];
            float* t1 = s_[2 * s8 + 1];
            uint32_t ph[4], pl[4];
            ph[0] = pack_hi(t0[0], t0[1]); pl[0] = pack_lo(t0[0], t0[1], ph[0]);
            ph[1] = pack_hi(t0[2], t0[3]); pl[1] = pack_lo(t0[2], t0[3], ph[1]);
            ph[2] = pack_hi(t1[0], t1[1]); pl[2] = pack_lo(t1[0], t1[1], ph[2]);
            ph[3] = pack_hi(t1[2], t1[3]); pl[3] = pack_lo(t1[2], t1[3], ph[3]);
            #pragma unroll
            for (int g = 0; g < 8; g++) {
                int vr = s8 * 16 + (l & 7) + ((l >> 3) & 1) * 8;
                int vc = 2 * g + ((l >> 4) & 1);
                uint32_t voff = stb + 32768 + vr * 256 + 16 * ((vc & 8) | ((vc ^ vr) & 7));
                uint32_t vh0, vh1, vh2, vh3, vl0, vl1, vl2, vl3;
                ldsm_x4t(vh0, vh1, vh2, vh3, voff);
                ldsm_x4t(vl0, vl1, vl2, vl3, voff + 16384);
                mma_bf16(O_[2 * g],     ph[0], ph[1], ph[2], ph[3], vh0, vh1);
                mma_bf16(O_[2 * g],     ph[0], ph[1], ph[2], ph[3], vl0, vl1);
                mma_bf16(O_[2 * g],     pl[0], pl[1], pl[2], pl[3], vh0, vh1);
                mma_bf16(O_[2 * g + 1], ph[0], ph[1], ph[2], ph[3], vh2, vh3);
                mma_bf16(O_[2 * g + 1], ph[0], ph[1], ph[2], ph[3], vl2, vl3);
                mma_bf16(O_[2 * g + 1], pl[0], pl[1], pl[2], pl[3], vh2, vh3);
            }
        }
        __syncthreads();
    }

    // ---- epilogue: out += O / L ----
    int b = bh >> 4, h = bh & 15;
    float inv0 = 1.f / L0, inv1 = 1.f / L1;
    int token = qt * 128 + w * 16 + (l >> 2);
    float* row0p = out + (size_t)(b * TT + token) * D_MODEL + h * HEAD;
    float* row1p = row0p + (size_t)8 * D_MODEL;
    #pragma unroll
    for (int t = 0; t < 16; t++) {
        int col = t * 8 + (l & 3) * 2;
        float2 v0 = *(float2*)(row0p + col);
        v0.x += O_[t][0] * inv0; v0.y += O_[t][1] * inv0;
        *(float2*)(row0p + col) = v0;
        float2 v1 = *(float2*)(row1p + col);
        v1.x += O_[t][2] * inv1; v1.y += O_[t][3] * inv1;
        *(float2*)(row1p + col) = v1;
    }
}

// ---------------- launch ----------------------------------------------------
extern "C" void kernel_launch(void* const* d_in, const int* in_sizes, int n_in,
                              void* d_out, int out_size) {
    const float* inputs = (const float*)d_in[0];
    const float* W_qkv  = (const float*)d_in[1];
    const float* b_qkv  = (const float*)d_in[2];
    const float* W_mlp  = (const float*)d_in[3];
    const float* b_mlp  = (const float*)d_in[4];
    float* out = (float*)d_out;

    void *pq, *pxh, *pxl, *pwqh, *pwql, *pwmh, *pwml, *phh, *phl;
    void *pqh, *pql, *pkh, *pkl, *pvh, *pvl;
    cudaGetSymbolAddress(&pq,  g_qkv);
    cudaGetSymbolAddress(&pxh, g_xh);  cudaGetSymbolAddress(&pxl, g_xl);
    cudaGetSymbolAddress(&pwqh, g_wqh); cudaGetSymbolAddress(&pwql, g_wql);
    cudaGetSymbolAddress(&pwmh, g_wmh); cudaGetSymbolAddress(&pwml, g_wml);
    cudaGetSymbolAddress(&phh, g_hh);  cudaGetSymbolAddress(&phl, g_hl);
    cudaGetSymbolAddress(&pqh, g_qh);  cudaGetSymbolAddress(&pql, g_ql);
    cudaGetSymbolAddress(&pkh, g_kh);  cudaGetSymbolAddress(&pkl, g_kl);
    cudaGetSymbolAddress(&pvh, g_vh);  cudaGetSymbolAddress(&pvl, g_vl);
    float* gq = (float*)pq;

    cudaFuncSetAttribute(tc_gemm3<true, false>,
                         cudaFuncAttributeMaxDynamicSharedMemorySize, GEMM_SMEM);
    cudaFuncSetAttribute(tc_gemm3<false, true>,
                         cudaFuncAttributeMaxDynamicSharedMemorySize, GEMM_SMEM);
    cudaFuncSetAttribute(flash3_kernel,
                         cudaFuncAttributeMaxDynamicSharedMemorySize, FLASH_SMEM);

    // 0) split weights
    split_kernel<<<(D_MODEL * QKV_OUT / 4) / 256, 256>>>(
        W_qkv, (__nv_bfloat16*)pwqh, (__nv_bfloat16*)pwql);
    split_kernel<<<(HIDDEN * D_MODEL / 4) / 256, 256>>>(
        W_mlp, (__nv_bfloat16*)pwmh, (__nv_bfloat16*)pwml);

    // 1) LN(inputs) -> split bf16
    ln_input_kernel<<<BT, 256>>>(inputs, (__nv_bfloat16*)pxh, (__nv_bfloat16*)pxl);

    // 2) qkv GEMM: q,k,v -> fp32 g_qkv; hidden -> fused GELU split bf16
    tc_gemm3<true, false><<<dim3(BT / 128, QKV_OUT / 128), 256, GEMM_SMEM>>>(
        (__nv_bfloat16*)pxh, (__nv_bfloat16*)pxl, D_MODEL,
        (__nv_bfloat16*)pwqh, (__nv_bfloat16*)pwql, QKV_OUT,
        gq, QKV3, b_qkv, nullptr,
        (__nv_bfloat16*)phh, (__nv_bfloat16*)phl, D_MODEL);

    // 3) q,k head-LN + split; v split (head-major)
    qkv_post_kernel<<<(3 * 65536) / 8, 256>>>(
        gq,
        (__nv_bfloat16*)pqh, (__nv_bfloat16*)pql,
        (__nv_bfloat16*)pkh, (__nv_bfloat16*)pkl,
        (__nv_bfloat16*)pvh, (__nv_bfloat16*)pvl);

    // 4) mlp GEMM: out = gelu_hidden @ W_mlp + b_mlp + inputs
    tc_gemm3<false, true><<<dim3(BT / 128, D_MODEL / 128), 256, GEMM_SMEM>>>(
        (__nv_bfloat16*)phh, (__nv_bfloat16*)phl, HIDDEN,
        (__nv_bfloat16*)pwmh, (__nv_bfloat16*)pwml, D_MODEL,
        out, D_MODEL, b_mlp, inputs, nullptr, nullptr, HIDDEN);

    // 5) out += attention
    flash3_kernel<<<dim3(TT / 128, BB * NUM_HEADS), 256, FLASH_SMEM>>>(
        (__nv_bfloat16*)pqh, (__nv_bfloat16*)pql,
        (__nv_bfloat16*)pkh, (__nv_bfloat16*)pkl,
        (__nv_bfloat16*)pvh, (__nv_bfloat16*)pvl, out);
}

// round 6
// speedup vs baseline: 3.3731x; 1.0425x over previous
#include <cuda_runtime.h>
#include <cuda_bf16.h>
#include <math.h>
#include <stdint.h>

#define D_MODEL   2048
#define NUM_HEADS 16
#define HEAD      128
#define FAN       4
#define QKV_OUT   (3 * D_MODEL + FAN * D_MODEL)   // 14336
#define HIDDEN    (FAN * D_MODEL)                 // 8192
#define BB        2
#define TT        2048
#define BT        (BB * TT)                       // 4096
#define QKV3      (3 * D_MODEL)                   // 6144

// ---------------- scratch (device globals) ---------------------------------
__device__ float         g_qkv[(size_t)BT * QKV3];           // fp32 q,k,v; later attn scratch
__device__ __nv_bfloat16 g_xh[(size_t)BT * D_MODEL];
__device__ __nv_bfloat16 g_xl[(size_t)BT * D_MODEL];
__device__ __nv_bfloat16 g_wqh[(size_t)D_MODEL * QKV_OUT];
__device__ __nv_bfloat16 g_wql[(size_t)D_MODEL * QKV_OUT];
__device__ __nv_bfloat16 g_wmh[(size_t)HIDDEN * D_MODEL];
__device__ __nv_bfloat16 g_wml[(size_t)HIDDEN * D_MODEL];
__device__ __nv_bfloat16 g_hh[(size_t)BT * HIDDEN];
__device__ __nv_bfloat16 g_hl[(size_t)BT * HIDDEN];
// head-major [b][h][t][d] split q/k/v for flash
__device__ __nv_bfloat16 g_qh[(size_t)BT * D_MODEL];
__device__ __nv_bfloat16 g_ql[(size_t)BT * D_MODEL];
__device__ __nv_bfloat16 g_kh[(size_t)BT * D_MODEL];
__device__ __nv_bfloat16 g_kl[(size_t)BT * D_MODEL];
__device__ __nv_bfloat16 g_vh[(size_t)BT * D_MODEL];
__device__ __nv_bfloat16 g_vl[(size_t)BT * D_MODEL];

// ---------------- PTX helpers ----------------------------------------------
__device__ __forceinline__ uint32_t smem_u32(const void* p) {
    uint32_t a;
    asm("{ .reg .u64 t; cvta.to.shared.u64 t, %1; cvt.u32.u64 %0, t; }"
        : "=r"(a) : "l"(p));
    return a;
}
__device__ __forceinline__ void cp16(uint32_t dst, const void* src) {
    asm volatile("cp.async.cg.shared.global [%0], [%1], 16;" :: "r"(dst), "l"(src));
}
#define CP_COMMIT() asm volatile("cp.async.commit_group;")
#define CP_WAIT0()  asm volatile("cp.async.wait_group 0;")
#define CP_WAIT1()  asm volatile("cp.async.wait_group 1;")

__device__ __forceinline__ void ldsm_x4(uint32_t& r0, uint32_t& r1,
                                        uint32_t& r2, uint32_t& r3, uint32_t addr) {
    asm volatile("ldmatrix.sync.aligned.m8n8.x4.shared.b16 {%0,%1,%2,%3}, [%4];"
                 : "=r"(r0), "=r"(r1), "=r"(r2), "=r"(r3) : "r"(addr));
}
__device__ __forceinline__ void ldsm_x4t(uint32_t& r0, uint32_t& r1,
                                         uint32_t& r2, uint32_t& r3, uint32_t addr) {
    asm volatile("ldmatrix.sync.aligned.m8n8.x4.trans.shared.b16 {%0,%1,%2,%3}, [%4];"
                 : "=r"(r0), "=r"(r1), "=r"(r2), "=r"(r3) : "r"(addr));
}
__device__ __forceinline__ void mma_bf16(float* d,
                                         uint32_t a0, uint32_t a1, uint32_t a2, uint32_t a3,
                                         uint32_t b0, uint32_t b1) {
    asm volatile(
        "mma.sync.aligned.m16n8k16.row.col.f32.bf16.bf16.f32 "
        "{%0,%1,%2,%3}, {%4,%5,%6,%7}, {%8,%9}, {%0,%1,%2,%3};"
        : "+f"(d[0]), "+f"(d[1]), "+f"(d[2]), "+f"(d[3])
        : "r"(a0), "r"(a1), "r"(a2), "r"(a3), "r"(b0), "r"(b1));
}
__device__ __forceinline__ uint32_t pack_hi(float x, float y) {
    __nv_bfloat162 h = __float22bfloat162_rn(make_float2(x, y));
    return *(uint32_t*)&h;
}
__device__ __forceinline__ uint32_t pack_lo(float x, float y, uint32_t hi) {
    __nv_bfloat162 h = *(__nv_bfloat162*)&hi;
    __nv_bfloat162 l = __float22bfloat162_rn(make_float2(
        x - __bfloat162float(h.x), y - __bfloat162float(h.y)));
    return *(uint32_t*)&l;
}
__device__ __forceinline__ float warp_sum(float v) {
    #pragma unroll
    for (int o = 16; o > 0; o >>= 1) v += __shfl_xor_sync(0xffffffffu, v, o);
    return v;
}
__device__ __forceinline__ float gelu_f(float x) {
    return 0.5f * x * (1.f + erff(x * 0.70710678118654752f));
}

// ---------------- 0) fp32 -> split bf16 (weights) ---------------------------
__global__ void split_kernel(const float* __restrict__ in,
                             __nv_bfloat16* __restrict__ oh,
                             __nv_bfloat16* __restrict__ ol) {
    int idx = blockIdx.x * blockDim.x + threadIdx.x;
    float4 v = ((const float4*)in)[idx];
    uint32_t h0 = pack_hi(v.x, v.y), h1 = pack_hi(v.z, v.w);
    uint32_t l0 = pack_lo(v.x, v.y, h0), l1 = pack_lo(v.z, v.w, h1);
    ((uint2*)oh)[idx] = make_uint2(h0, h1);
    ((uint2*)ol)[idx] = make_uint2(l0, l1);
}

// ---------------- 1) LayerNorm(inputs) -> split bf16 ------------------------
__global__ void ln_input_kernel(const float* __restrict__ in,
                                __nv_bfloat16* __restrict__ oh,
                                __nv_bfloat16* __restrict__ ol) {
    int row = blockIdx.x;
    const float4* src = (const float4*)(in + (size_t)row * D_MODEL);

    float4 v[2];
    float s = 0.f, sq = 0.f;
    #pragma unroll
    for (int i = 0; i < 2; i++) {
        v[i] = src[threadIdx.x + i * 256];
        s  += v[i].x + v[i].y + v[i].z + v[i].w;
        sq += v[i].x * v[i].x + v[i].y * v[i].y + v[i].z * v[i].z + v[i].w * v[i].w;
    }
    __shared__ float sh_s[8], sh_q[8];
    int lane = threadIdx.x & 31, wid = threadIdx.x >> 5;
    s = warp_sum(s); sq = warp_sum(sq);
    if (lane == 0) { sh_s[wid] = s; sh_q[wid] = sq; }
    __syncthreads();
    if (wid == 0) {
        float a = (lane < 8) ? sh_s[lane] : 0.f;
        float b = (lane < 8) ? sh_q[lane] : 0.f;
        a = warp_sum(a); b = warp_sum(b);
        if (lane == 0) { sh_s[0] = a; sh_q[0] = b; }
    }
    __syncthreads();
    float mean = sh_s[0] * (1.f / D_MODEL);
    float var  = sh_q[0] * (1.f / D_MODEL) - mean * mean;
    float r    = rsqrtf(var + 1e-5f);
    #pragma unroll
    for (int i = 0; i < 2; i++) {
        float a = (v[i].x - mean) * r, b = (v[i].y - mean) * r;
        float c = (v[i].z - mean) * r, d = (v[i].w - mean) * r;
        uint32_t h0 = pack_hi(a, b), h1 = pack_hi(c, d);
        uint32_t l0 = pack_lo(a, b, h0), l1 = pack_lo(c, d, h1);
        size_t o = (size_t)row * (D_MODEL / 4) + threadIdx.x + i * 256;
        ((uint2*)oh)[o] = make_uint2(h0, h1);
        ((uint2*)ol)[o] = make_uint2(l0, l1);
    }
}

// ============================================================================
// 2) 3-stage cp.async split-bf16 tensor GEMM with register pipelining.
//    CTA 128x128, kstage=32. QKV mode: hidden cols -> fused GELU + split.
// ============================================================================
#define GSTAGE 32768
#define GEMM_SMEM (3 * GSTAGE)

template<bool QKV, bool ADD_RES>
__global__ __launch_bounds__(256, 2)
void tc_gemm3(const __nv_bfloat16* __restrict__ Ah, const __nv_bfloat16* __restrict__ Al,
              int lda,
              const __nv_bfloat16* __restrict__ Bh, const __nv_bfloat16* __restrict__ Bl,
              int ldb,
              float* __restrict__ C, int ldc,
              const float* __restrict__ bias,
              const float* __restrict__ res,
              __nv_bfloat16* __restrict__ Hh, __nv_bfloat16* __restrict__ Hl,
              int K) {
    extern __shared__ char gsm[];
    const uint32_t smb = smem_u32(gsm);

    const int tid = threadIdx.x;
    const int l = tid & 31, w = tid >> 5;
    const int wm = (w & 3) * 32;
    const int wn = (w >> 2) * 64;
    const int bm = blockIdx.x * 128, bn = blockIdx.y * 128;

    const int ar = tid >> 1;
    const int ac0 = (tid & 1) * 2;
    const int br = tid >> 3;
    const int bc0 = (tid & 7) * 2;

    float acc[2][8][4];
    #pragma unroll
    for (int mt = 0; mt < 2; mt++)
        #pragma unroll
        for (int nt = 0; nt < 8; nt++)
            #pragma unroll
            for (int e = 0; e < 4; e++) acc[mt][nt][e] = 0.f;

    const int nkb = K / 32;

    auto issue = [&](int stage, int k0) {
        uint32_t sb = smb + stage * GSTAGE;
        #pragma unroll
        for (int j = 0; j < 2; j++) {
            int c = ac0 + j;
            uint32_t dst = sb + ar * 64 + 16 * (c ^ ((ar >> 1) & 3));
            cp16(dst,        Ah + (size_t)(bm + ar) * lda + k0 + c * 8);
            cp16(dst + 8192, Al + (size_t)(bm + ar) * lda + k0 + c * 8);
        }
        #pragma unroll
        for (int j = 0; j < 2; j++) {
            int c = bc0 + j;
            uint32_t dst = sb + 16384 + br * 256 + 16 * ((c & 8) | ((c ^ br) & 7));
            cp16(dst,        Bh + (size_t)(k0 + br) * ldb + bn + c * 8);
            cp16(dst + 8192, Bl + (size_t)(k0 + br) * ldb + bn + c * 8);
        }
    };

    issue(0, 0);  CP_COMMIT();
    issue(1, 32); CP_COMMIT();

    int cur = 0, iss = 2;
    for (int kb = 0; kb < nkb; kb++) {
        if (kb + 1 < nkb) { CP_WAIT1(); } else { CP_WAIT0(); }
        __syncthreads();
        if (kb + 2 < nkb) { issue(iss, (kb + 2) * 32); CP_COMMIT(); }

        uint32_t sb = smb + cur * GSTAGE;

        auto ldB = [&](int ks, int p, uint32_t* BHp, uint32_t* BLp) {
            int g = (w >> 2) * 4 + p;
            int kk = ks * 16 + (l & 7) + ((l >> 3) & 1) * 8;
            int c = 2 * g + ((l >> 4) & 1);
            uint32_t off = sb + 16384 + kk * 256 + 16 * ((c & 8) | ((c ^ kk) & 7));
            ldsm_x4t(BHp[0], BHp[1], BHp[2], BHp[3], off);
            ldsm_x4t(BLp[0], BLp[1], BLp[2], BLp[3], off + 8192);
        };

        #pragma unroll
        for (int ks = 0; ks < 2; ks++) {
            uint32_t AH[2][4], AL[2][4];
            #pragma unroll
            for (int mt = 0; mt < 2; mt++) {
                int r = wm + mt * 16 + (l & 15);
                int c = ks * 2 + (l >> 4);
                uint32_t off = sb + r * 64 + 16 * (c ^ ((r >> 1) & 3));
                ldsm_x4(AH[mt][0], AH[mt][1], AH[mt][2], AH[mt][3], off);
                ldsm_x4(AL[mt][0], AL[mt][1], AL[mt][2], AL[mt][3], off + 8192);
            }
            uint32_t BHf[2][4], BLf[2][4];
            ldB(ks, 0, BHf[0], BLf[0]);
            #pragma unroll
            for (int p = 0; p < 4; p++) {
                if (p < 3) ldB(ks, p + 1, BHf[(p + 1) & 1], BLf[(p + 1) & 1]);
                const uint32_t* bh = BHf[p & 1];
                const uint32_t* bl = BLf[p & 1];
                #pragma unroll
                for (int mt = 0; mt < 2; mt++) {
                    mma_bf16(acc[mt][p * 2],     AH[mt][0], AH[mt][1], AH[mt][2], AH[mt][3], bh[0], bh[1]);
                    mma_bf16(acc[mt][p * 2],     AH[mt][0], AH[mt][1], AH[mt][2], AH[mt][3], bl[0], bl[1]);
                    mma_bf16(acc[mt][p * 2],     AL[mt][0], AL[mt][1], AL[mt][2], AL[mt][3], bh[0], bh[1]);
                    mma_bf16(acc[mt][p * 2 + 1], AH[mt][0], AH[mt][1], AH[mt][2], AH[mt][3], bh[2], bh[3]);
                    mma_bf16(acc[mt][p * 2 + 1], AH[mt][0], AH[mt][1], AH[mt][2], AH[mt][3], bl[2], bl[3]);
                    mma_bf16(acc[mt][p * 2 + 1], AL[mt][0], AL[mt][1], AL[mt][2], AL[mt][3], bh[2], bh[3]);
                }
            }
        }
        cur = (cur + 1 == 3) ? 0 : cur + 1;
        iss = (iss + 1 == 3) ? 0 : iss + 1;
    }

    // ---- epilogue ----
    if (QKV && bn >= QKV3) {
        #pragma unroll
        for (int mt = 0; mt < 2; mt++) {
            int row0 = bm + wm + mt * 16 + (l >> 2);
            #pragma unroll
            for (int nt = 0; nt < 8; nt++) {
                int col = bn + wn + nt * 8 + (l & 3) * 2;
                int hcol = col - QKV3;
                float b0 = bias[col], b1 = bias[col + 1];
                float* d = acc[mt][nt];
                float a0 = gelu_f(d[0] + b0), a1 = gelu_f(d[1] + b1);
                float a2 = gelu_f(d[2] + b0), a3 = gelu_f(d[3] + b1);
                uint32_t h0 = pack_hi(a0, a1), lo0 = pack_lo(a0, a1, h0);
                uint32_t h1 = pack_hi(a2, a3), lo1 = pack_lo(a2, a3, h1);
                *(uint32_t*)(Hh + (size_t)row0 * HIDDEN + hcol) = h0;
                *(uint32_t*)(Hl + (size_t)row0 * HIDDEN + hcol) = lo0;
                *(uint32_t*)(Hh + (size_t)(row0 + 8) * HIDDEN + hcol) = h1;
                *(uint32_t*)(Hl + (size_t)(row0 + 8) * HIDDEN + hcol) = lo1;
            }
        }
    } else {
        #pragma unroll
        for (int mt = 0; mt < 2; mt++) {
            int row0 = bm + wm + mt * 16 + (l >> 2);
            #pragma unroll
            for (int nt = 0; nt < 8; nt++) {
                int col = bn + wn + nt * 8 + (l & 3) * 2;
                float b0 = bias[col], b1 = bias[col + 1];
                float* d = acc[mt][nt];
                float2 o0 = make_float2(d[0] + b0, d[1] + b1);
                float2 o1 = make_float2(d[2] + b0, d[3] + b1);
                if (ADD_RES) {
                    float2 r0 = *(const float2*)(res + (size_t)row0 * ldc + col);
                    float2 r1 = *(const float2*)(res + (size_t)(row0 + 8) * ldc + col);
                    o0.x += r0.x; o0.y += r0.y;
                    o1.x += r1.x; o1.y += r1.y;
                }
                *(float2*)(C + (size_t)row0 * ldc + col) = o0;
                *(float2*)(C + (size_t)(row0 + 8) * ldc + col) = o1;
            }
        }
    }
}

// ---------------- 3) q,k head-LN + split; v split (head-major out) ----------
// q additionally pre-scaled by 1/sqrt(HEAD).
__global__ void qkv_post_kernel(const float* __restrict__ qkv,
                                __nv_bfloat16* __restrict__ qh, __nv_bfloat16* __restrict__ ql,
                                __nv_bfloat16* __restrict__ kh, __nv_bfloat16* __restrict__ kl,
                                __nv_bfloat16* __restrict__ vh, __nv_bfloat16* __restrict__ vl) {
    int gw   = (blockIdx.x * blockDim.x + threadIdx.x) >> 5;
    int lane = threadIdx.x & 31;
    int seg   = gw >> 16;        // 0=q, 1=k, 2=v
    int r     = gw & 65535;
    int token = r >> 4;
    int h     = r & 15;
    const float* base = qkv + (size_t)token * QKV3 + seg * D_MODEL + h * HEAD;
    float4 v = ((const float4*)base)[lane];
    if (seg < 2) {
        float s = warp_sum(v.x + v.y + v.z + v.w) * (1.f / HEAD);
        float d0 = v.x - s, d1 = v.y - s, d2 = v.z - s, d3 = v.w - s;
        float var = warp_sum(d0 * d0 + d1 * d1 + d2 * d2 + d3 * d3) * (1.f / HEAD);
        float rr = rsqrtf(var + 1e-5f);
        if (seg == 0) rr *= 0.08838834764831845f;   // fold 1/sqrt(HEAD) into q
        v = make_float4(d0 * rr, d1 * rr, d2 * rr, d3 * rr);
    }
    int b = token >> 11, tt = token & 2047;
    size_t o = ((((size_t)b * 16 + h) * 2048 + tt) * 128 + lane * 4) >> 2;
    uint32_t h0 = pack_hi(v.x, v.y), h1 = pack_hi(v.z, v.w);
    uint32_t l0 = pack_lo(v.x, v.y, h0), l1 = pack_lo(v.z, v.w, h1);
    __nv_bfloat16* oh = (seg == 0) ? qh : (seg == 1) ? kh : vh;
    __nv_bfloat16* ol = (seg == 0) ? ql : (seg == 1) ? kl : vl;
    ((uint2*)oh)[o] = make_uint2(h0, h1);
    ((uint2*)ol)[o] = make_uint2(l0, l1);
}

// ============================================================================
// 4) flash v4: Q frags hoisted to registers; writes attn to scratch (no RMW)
// ============================================================================
#define FLASH_SMEM 196608   // Q hi/lo 64KB + 2 stages x (K,V hi/lo) 64KB

__global__ __launch_bounds__(256, 1)
void flash4_kernel(const __nv_bfloat16* __restrict__ qh, const __nv_bfloat16* __restrict__ ql,
                   const __nv_bfloat16* __restrict__ kh, const __nv_bfloat16* __restrict__ kl,
                   const __nv_bfloat16* __restrict__ vh, const __nv_bfloat16* __restrict__ vl,
                   float* __restrict__ attn) {
    extern __shared__ char fsm[];
    const uint32_t sb = smem_u32(fsm);
    const int tid = threadIdx.x;
    const int l = tid & 31, w = tid >> 5;
    const int qt = (int)gridDim.x - 1 - (int)blockIdx.x;
    const int bh = blockIdx.y;
    const size_t hbase = (size_t)bh * 2048 * 128;

    // ---- issue Q (128 rows x 256B, hi+lo) ----
    {
        int row = tid >> 1, half = tid & 1;
        const __nv_bfloat16* sq = qh + hbase + (size_t)(qt * 128 + row) * 128;
        const __nv_bfloat16* sl = ql + hbase + (size_t)(qt * 128 + row) * 128;
        #pragma unroll
        for (int j = 0; j < 8; j++) {
            int c = half * 8 + j;
            uint32_t dst = sb + row * 256 + 16 * ((c & 8) | ((c ^ row) & 7));
            cp16(dst,         sq + c * 8);
            cp16(dst + 32768, sl + c * 8);
        }
    }
    CP_COMMIT();
    auto issue_kv = [&](int stage, int kt) {
        uint32_t stb = sb + 65536 + stage * 65536;
        int r = tid >> 2, q4 = tid & 3;
        const __nv_bfloat16* pkh = kh + hbase + (size_t)(kt * 64 + r) * 128;
        const __nv_bfloat16* pkl = kl + hbase + (size_t)(kt * 64 + r) * 128;
        const __nv_bfloat16* pvh = vh + hbase + (size_t)(kt * 64 + r) * 128;
        const __nv_bfloat16* pvl = vl + hbase + (size_t)(kt * 64 + r) * 128;
        #pragma unroll
        for (int j = 0; j < 4; j++) {
            int c = q4 * 4 + j;
            uint32_t sw = r * 256 + 16 * ((c & 8) | ((c ^ r) & 7));
            cp16(stb + sw,         pkh + c * 8);
            cp16(stb + 16384 + sw, pkl + c * 8);
            cp16(stb + 32768 + sw, pvh + c * 8);
            cp16(stb + 49152 + sw, pvl + c * 8);
        }
    };
    issue_kv(0, 0);
    CP_COMMIT();

    // ---- hoist Q fragments (hi+lo) into registers for the whole sweep ----
    uint32_t QH[8][4], QL[8][4];
    CP_WAIT1();           // Q group complete
    __syncthreads();
    {
        int qr = w * 16 + (l & 15);
        #pragma unroll
        for (int ks = 0; ks < 8; ks++) {
            int qc = ks * 2 + (l >> 4);
            uint32_t qoff = sb + qr * 256 + 16 * ((qc & 8) | ((qc ^ qr) & 7));
            ldsm_x4(QH[ks][0], QH[ks][1], QH[ks][2], QH[ks][3], qoff);
            ldsm_x4(QL[ks][0], QL[ks][1], QL[ks][2], QL[ks][3], qoff + 32768);
        }
    }

    float O_[16][4];
    #pragma unroll
    for (int t = 0; t < 16; t++)
        #pragma unroll
        for (int e = 0; e < 4; e++) O_[t][e] = 0.f;
    float M0 = -INFINITY, M1 = -INFINITY, L0 = 0.f, L1 = 0.f;
    const int ktmax = 2 * qt + 1;

    for (int kt = 0; kt <= ktmax; kt++) {
        CP_WAIT0();
        __syncthreads();
        if (kt < ktmax) { issue_kv((kt + 1) & 1, kt + 1); CP_COMMIT(); }

        uint32_t stb = sb + 65536 + (kt & 1) * 65536;

        // ---- S = Q K^T ----
        float s_[8][4];
        #pragma unroll
        for (int t = 0; t < 8; t++)
            #pragma unroll
            for (int e = 0; e < 4; e++) s_[t][e] = 0.f;

        #pragma unroll
        for (int ks = 0; ks < 8; ks++) {
            #pragma unroll
            for (int g = 0; g < 4; g++) {
                int kr = g * 16 + (l & 7) + ((l >> 4) & 1) * 8;
                int kc = ks * 2 + ((l >> 3) & 1);
                uint32_t koff = stb + kr * 256 + 16 * ((kc & 8) | ((kc ^ kr) & 7));
                uint32_t bh0, bh1, bh2, bh3, bl0, bl1, bl2, bl3;
                ldsm_x4(bh0, bh1, bh2, bh3, koff);
                ldsm_x4(bl0, bl1, bl2, bl3, koff + 16384);
                mma_bf16(s_[2 * g],     QH[ks][0], QH[ks][1], QH[ks][2], QH[ks][3], bh0, bh1);
                mma_bf16(s_[2 * g],     QH[ks][0], QH[ks][1], QH[ks][2], QH[ks][3], bl0, bl1);
                mma_bf16(s_[2 * g],     QL[ks][0], QL[ks][1], QL[ks][2], QL[ks][3], bh0, bh1);
                mma_bf16(s_[2 * g + 1], QH[ks][0], QH[ks][1], QH[ks][2], QH[ks][3], bh2, bh3);
                mma_bf16(s_[2 * g + 1], QH[ks][0], QH[ks][1], QH[ks][2], QH[ks][3], bl2, bl3);
                mma_bf16(s_[2 * g + 1], QL[ks][0], QL[ks][1], QL[ks][2], QL[ks][3], bh2, bh3);
            }
        }

        if (kt >= 2 * qt) {           // diagonal region: element mask
            int qr0 = qt * 128 + w * 16 + (l >> 2);
            int qr1 = qr0 + 8;
            #pragma unroll
            for (int t = 0; t < 8; t++) {
                int kc = kt * 64 + t * 8 + (l & 3) * 2;
                if (kc     > qr0) s_[t][0] = -INFINITY;
                if (kc + 1 > qr0) s_[t][1] = -INFINITY;
                if (kc     > qr1) s_[t][2] = -INFINITY;
                if (kc + 1 > qr1) s_[t][3] = -INFINITY;
            }
        }

        // ---- online softmax ----
        float m0 = -INFINITY, m1 = -INFINITY;
        #pragma unroll
        for (int t = 0; t < 8; t++) {
            m0 = fmaxf(m0, fmaxf(s_[t][0], s_[t][1]));
            m1 = fmaxf(m1, fmaxf(s_[t][2], s_[t][3]));
        }
        #pragma unroll
        for (int o = 1; o < 4; o <<= 1) {
            m0 = fmaxf(m0, __shfl_xor_sync(0xffffffffu, m0, o));
            m1 = fmaxf(m1, __shfl_xor_sync(0xffffffffu, m1, o));
        }
        float nm0 = fmaxf(M0, m0), nm1 = fmaxf(M1, m1);
        float corr0 = __expf(M0 - nm0), corr1 = __expf(M1 - nm1);
        M0 = nm0; M1 = nm1;

        float ps0 = 0.f, ps1 = 0.f;
        #pragma unroll
        for (int t = 0; t < 8; t++) {
            s_[t][0] = __expf(s_[t][0] - nm0); ps0 += s_[t][0];
            s_[t][1] = __expf(s_[t][1] - nm0); ps0 += s_[t][1];
            s_[t][2] = __expf(s_[t][2] - nm1); ps1 += s_[t][2];
            s_[t][3] = __expf(s_[t][3] - nm1); ps1 += s_[t][3];
        }
        #pragma unroll
        for (int o = 1; o < 4; o <<= 1) {
            ps0 += __shfl_xor_sync(0xffffffffu, ps0, o);
            ps1 += __shfl_xor_sync(0xffffffffu, ps1, o);
        }
        L0 = L0 * corr0 + ps0;
        L1 = L1 * corr1 + ps1;
        #pragma unroll
        for (int t = 0; t < 16; t++) {
            O_[t][0] *= corr0; O_[t][1] *= corr0;
            O_[t][2] *= corr1; O_[t][3] *= corr1;
        }

        // ---- O += P V ----
        #pragma unroll
        for (int s8 = 0; s8 < 4; s8++) {
            float* t0 = s_[2 * s8];
            float* t1 = s_[2 * s8 + 1];
            uint32_t ph[4], pl[4];
            ph[0] = pack_hi(t0[0], t0[1]); pl[0] = pack_lo(t0[0], t0[1], ph[0]);
            ph[1] = pack_hi(t0[2], t0[3]); pl[1] = pack_lo(t0[2], t0[3], ph[1]);
            ph[2] = pack_hi(t1[0], t1[1]); pl[2] = pack_lo(t1[0], t1[1], ph[2]);
            ph[3] = pack_hi(t1[2], t1[3]); pl[3] = pack_lo(t1[2], t1[3], ph[3]);
            #pragma unroll
            for (int g = 0; g < 8; g++) {
                int vr = s8 * 16 + (l & 7) + ((l >> 3) & 1) * 8;
                int vc = 2 * g + ((l >> 4) & 1);
                uint32_t voff = stb + 32768 + vr * 256 + 16 * ((vc & 8) | ((vc ^ vr) & 7));
                uint32_t vh0, vh1, vh2, vh3, vl0, vl1, vl2, vl3;
                ldsm_x4t(vh0, vh1, vh2, vh3, voff);
                ldsm_x4t(vl0, vl1, vl2, vl3, voff + 16384);
                mma_bf16(O_[2 * g],     ph[0], ph[1], ph[2], ph[3], vh0, vh1);
                mma_bf16(O_[2 * g],     ph[0], ph[1], ph[2], ph[3], vl0, vl1);
                mma_bf16(O_[2 * g],     pl[0], pl[1], pl[2], pl[3], vh0, vh1);
                mma_bf16(O_[2 * g + 1], ph[0], ph[1], ph[2], ph[3], vh2, vh3);
                mma_bf16(O_[2 * g + 1], ph[0], ph[1], ph[2], ph[3], vl2, vl3);
                mma_bf16(O_[2 * g + 1], pl[0], pl[1], pl[2], pl[3], vh2, vh3);
            }
        }
    }

    // ---- epilogue: attn = O / L (plain store, no RMW) ----
    int b = bh >> 4, h = bh & 15;
    float inv0 = 1.f / L0, inv1 = 1.f / L1;
    int token = qt * 128 + w * 16 + (l >> 2);
    float* row0p = attn + (size_t)(b * TT + token) * D_MODEL + h * HEAD;
    float* row1p = row0p + (size_t)8 * D_MODEL;
    #pragma unroll
    for (int t = 0; t < 16; t++) {
        int col = t * 8 + (l & 3) * 2;
        *(float2*)(row0p + col) = make_float2(O_[t][0] * inv0, O_[t][1] * inv0);
        *(float2*)(row1p + col) = make_float2(O_[t][2] * inv1, O_[t][3] * inv1);
    }
}

// ---------------- 5) out += attn --------------------------------------------
__global__ void attn_add_kernel(float* __restrict__ out, const float* __restrict__ attn) {
    int idx = blockIdx.x * blockDim.x + threadIdx.x;
    float4 o = ((float4*)out)[idx];
    float4 a = ((const float4*)attn)[idx];
    o.x += a.x; o.y += a.y; o.z += a.z; o.w += a.w;
    ((float4*)out)[idx] = o;
}

// ---------------- launch ----------------------------------------------------
extern "C" void kernel_launch(void* const* d_in, const int* in_sizes, int n_in,
                              void* d_out, int out_size) {
    const float* inputs = (const float*)d_in[0];
    const float* W_qkv  = (const float*)d_in[1];
    const float* b_qkv  = (const float*)d_in[2];
    const float* W_mlp  = (const float*)d_in[3];
    const float* b_mlp  = (const float*)d_in[4];
    float* out = (float*)d_out;

    void *pq, *pxh, *pxl, *pwqh, *pwql, *pwmh, *pwml, *phh, *phl;
    void *pqh, *pql, *pkh, *pkl, *pvh, *pvl;
    cudaGetSymbolAddress(&pq,  g_qkv);
    cudaGetSymbolAddress(&pxh, g_xh);  cudaGetSymbolAddress(&pxl, g_xl);
    cudaGetSymbolAddress(&pwqh, g_wqh); cudaGetSymbolAddress(&pwql, g_wql);
    cudaGetSymbolAddress(&pwmh, g_wmh); cudaGetSymbolAddress(&pwml, g_wml);
    cudaGetSymbolAddress(&phh, g_hh);  cudaGetSymbolAddress(&phl, g_hl);
    cudaGetSymbolAddress(&pqh, g_qh);  cudaGetSymbolAddress(&pql, g_ql);
    cudaGetSymbolAddress(&pkh, g_kh);  cudaGetSymbolAddress(&pkl, g_kl);
    cudaGetSymbolAddress(&pvh, g_vh);  cudaGetSymbolAddress(&pvl, g_vl);
    float* gq = (float*)pq;
    float* gattn = gq;   // reuse q/k/v fp32 scratch as attention output

    cudaFuncSetAttribute(tc_gemm3<true, false>,
                         cudaFuncAttributeMaxDynamicSharedMemorySize, GEMM_SMEM);
    cudaFuncSetAttribute(tc_gemm3<false, true>,
                         cudaFuncAttributeMaxDynamicSharedMemorySize, GEMM_SMEM);
    cudaFuncSetAttribute(flash4_kernel,
                         cudaFuncAttributeMaxDynamicSharedMemorySize, FLASH_SMEM);

    // fork-join stream for the MLP branch (created per call; not destroyed to
    // stay capture-safe — kernel_launch runs only for correctness + capture)
    cudaStream_t s1;
    cudaStreamCreateWithFlags(&s1, cudaStreamNonBlocking);
    cudaEvent_t e0, e1;
    cudaEventCreateWithFlags(&e0, cudaEventDisableTiming);
    cudaEventCreateWithFlags(&e1, cudaEventDisableTiming);

    // 0) split weights
    split_kernel<<<(D_MODEL * QKV_OUT / 4) / 256, 256>>>(
        W_qkv, (__nv_bfloat16*)pwqh, (__nv_bfloat16*)pwql);
    split_kernel<<<(HIDDEN * D_MODEL / 4) / 256, 256>>>(
        W_mlp, (__nv_bfloat16*)pwmh, (__nv_bfloat16*)pwml);

    // 1) LN(inputs) -> split bf16
    ln_input_kernel<<<BT, 256>>>(inputs, (__nv_bfloat16*)pxh, (__nv_bfloat16*)pxl);

    // 2) qkv GEMM: q,k,v -> fp32 g_qkv; hidden -> fused GELU split bf16
    tc_gemm3<true, false><<<dim3(BT / 128, QKV_OUT / 128), 256, GEMM_SMEM>>>(
        (__nv_bfloat16*)pxh, (__nv_bfloat16*)pxl, D_MODEL,
        (__nv_bfloat16*)pwqh, (__nv_bfloat16*)pwql, QKV_OUT,
        gq, QKV3, b_qkv, nullptr,
        (__nv_bfloat16*)phh, (__nv_bfloat16*)phl, D_MODEL);

    // ---- fork: MLP on s1 ----
    cudaEventRecord(e0, 0);
    cudaStreamWaitEvent(s1, e0, 0);
    tc_gemm3<false, true><<<dim3(BT / 128, D_MODEL / 128), 256, GEMM_SMEM, s1>>>(
        (__nv_bfloat16*)phh, (__nv_bfloat16*)phl, HIDDEN,
        (__nv_bfloat16*)pwmh, (__nv_bfloat16*)pwml, D_MODEL,
        out, D_MODEL, b_mlp, inputs, nullptr, nullptr, HIDDEN);
    cudaEventRecord(e1, s1);

    // ---- main stream: attention branch ----
    // 3) q,k head-LN + split (q pre-scaled); v split (head-major)
    qkv_post_kernel<<<(3 * 65536) / 8, 256>>>(
        gq,
        (__nv_bfloat16*)pqh, (__nv_bfloat16*)pql,
        (__nv_bfloat16*)pkh, (__nv_bfloat16*)pkl,
        (__nv_bfloat16*)pvh, (__nv_bfloat16*)pvl);

    // 4) attn = attention(q, k, v)  (g_qkv no longer needed -> reuse as scratch)
    flash4_kernel<<<dim3(TT / 128, BB * NUM_HEADS), 256, FLASH_SMEM>>>(
        (__nv_bfloat16*)pqh, (__nv_bfloat16*)pql,
        (__nv_bfloat16*)pkh, (__nv_bfloat16*)pkl,
        (__nv_bfloat16*)pvh, (__nv_bfloat16*)pvl, gattn);

    // ---- join, then out += attn ----
    cudaStreamWaitEvent(0, e1, 0);
    attn_add_kernel<<<(BT * D_MODEL / 4) / 256, 256>>>(out, gattn);
}

// round 7
// speedup vs baseline: 8.1710x; 2.4224x over previous
#include <cuda_runtime.h>
#include <cuda_fp16.h>
#include <math.h>
#include <stdint.h>

#define D_MODEL   2048
#define NUM_HEADS 16
#define HEAD      128
#define FAN       4
#define QKV_OUT   (3 * D_MODEL + FAN * D_MODEL)   // 14336
#define HIDDEN    (FAN * D_MODEL)                 // 8192
#define BB        2
#define TT        2048
#define BT        (BB * TT)                       // 4096
#define QKV3      (3 * D_MODEL)                   // 6144

// ---------------- scratch (device globals) ---------------------------------
__device__ float  g_qkv[(size_t)BT * QKV3];       // fp32 q,k,v; later attn scratch
__device__ __half g_x[(size_t)BT * D_MODEL];
__device__ __half g_wq[(size_t)D_MODEL * QKV_OUT];
__device__ __half g_wm[(size_t)HIDDEN * D_MODEL];
__device__ __half g_h[(size_t)BT * HIDDEN];
// head-major [b][h][t][d] q/k/v for flash
__device__ __half g_q[(size_t)BT * D_MODEL];
__device__ __half g_k[(size_t)BT * D_MODEL];
__device__ __half g_v[(size_t)BT * D_MODEL];

// ---------------- PTX helpers ----------------------------------------------
__device__ __forceinline__ uint32_t smem_u32(const void* p) {
    uint32_t a;
    asm("{ .reg .u64 t; cvta.to.shared.u64 t, %1; cvt.u32.u64 %0, t; }"
        : "=r"(a) : "l"(p));
    return a;
}
__device__ __forceinline__ void cp16(uint32_t dst, const void* src) {
    asm volatile("cp.async.cg.shared.global [%0], [%1], 16;" :: "r"(dst), "l"(src));
}
#define CP_COMMIT() asm volatile("cp.async.commit_group;")
#define CP_WAIT0()  asm volatile("cp.async.wait_group 0;")
#define CP_WAIT1()  asm volatile("cp.async.wait_group 1;")
#define CP_WAIT2()  asm volatile("cp.async.wait_group 2;")

__device__ __forceinline__ void ldsm_x4(uint32_t& r0, uint32_t& r1,
                                        uint32_t& r2, uint32_t& r3, uint32_t addr) {
    asm volatile("ldmatrix.sync.aligned.m8n8.x4.shared.b16 {%0,%1,%2,%3}, [%4];"
                 : "=r"(r0), "=r"(r1), "=r"(r2), "=r"(r3) : "r"(addr));
}
__device__ __forceinline__ void ldsm_x4t(uint32_t& r0, uint32_t& r1,
                                         uint32_t& r2, uint32_t& r3, uint32_t addr) {
    asm volatile("ldmatrix.sync.aligned.m8n8.x4.trans.shared.b16 {%0,%1,%2,%3}, [%4];"
                 : "=r"(r0), "=r"(r1), "=r"(r2), "=r"(r3) : "r"(addr));
}
__device__ __forceinline__ void mma_f16(float* d,
                                        uint32_t a0, uint32_t a1, uint32_t a2, uint32_t a3,
                                        uint32_t b0, uint32_t b1) {
    asm volatile(
        "mma.sync.aligned.m16n8k16.row.col.f32.f16.f16.f32 "
        "{%0,%1,%2,%3}, {%4,%5,%6,%7}, {%8,%9}, {%0,%1,%2,%3};"
        : "+f"(d[0]), "+f"(d[1]), "+f"(d[2]), "+f"(d[3])
        : "r"(a0), "r"(a1), "r"(a2), "r"(a3), "r"(b0), "r"(b1));
}
__device__ __forceinline__ uint32_t pack_h(float x, float y) {
    __half2 h = __float22half2_rn(make_float2(x, y));
    return *(uint32_t*)&h;
}
__device__ __forceinline__ float warp_sum(float v) {
    #pragma unroll
    for (int o = 16; o > 0; o >>= 1) v += __shfl_xor_sync(0xffffffffu, v, o);
    return v;
}
__device__ __forceinline__ float gelu_f(float x) {
    return 0.5f * x * (1.f + erff(x * 0.70710678118654752f));
}

// ---------------- 0) fp32 -> fp16 convert (weights) -------------------------
__global__ void convert_kernel(const float* __restrict__ in, __half* __restrict__ oh) {
    int idx = blockIdx.x * blockDim.x + threadIdx.x;
    float4 v = ((const float4*)in)[idx];
    ((uint2*)oh)[idx] = make_uint2(pack_h(v.x, v.y), pack_h(v.z, v.w));
}

// ---------------- 1) LayerNorm(inputs) -> fp16 ------------------------------
__global__ void ln_input_kernel(const float* __restrict__ in, __half* __restrict__ oh) {
    int row = blockIdx.x;
    const float4* src = (const float4*)(in + (size_t)row * D_MODEL);

    float4 v[2];
    float s = 0.f, sq = 0.f;
    #pragma unroll
    for (int i = 0; i < 2; i++) {
        v[i] = src[threadIdx.x + i * 256];
        s  += v[i].x + v[i].y + v[i].z + v[i].w;
        sq += v[i].x * v[i].x + v[i].y * v[i].y + v[i].z * v[i].z + v[i].w * v[i].w;
    }
    __shared__ float sh_s[8], sh_q[8];
    int lane = threadIdx.x & 31, wid = threadIdx.x >> 5;
    s = warp_sum(s); sq = warp_sum(sq);
    if (lane == 0) { sh_s[wid] = s; sh_q[wid] = sq; }
    __syncthreads();
    if (wid == 0) {
        float a = (lane < 8) ? sh_s[lane] : 0.f;
        float b = (lane < 8) ? sh_q[lane] : 0.f;
        a = warp_sum(a); b = warp_sum(b);
        if (lane == 0) { sh_s[0] = a; sh_q[0] = b; }
    }
    __syncthreads();
    float mean = sh_s[0] * (1.f / D_MODEL);
    float var  = sh_q[0] * (1.f / D_MODEL) - mean * mean;
    float r    = rsqrtf(var + 1e-5f);
    #pragma unroll
    for (int i = 0; i < 2; i++) {
        float a = (v[i].x - mean) * r, b = (v[i].y - mean) * r;
        float c = (v[i].z - mean) * r, d = (v[i].w - mean) * r;
        size_t o = (size_t)row * (D_MODEL / 4) + threadIdx.x + i * 256;
        ((uint2*)oh)[o] = make_uint2(pack_h(a, b), pack_h(c, d));
    }
}

// ============================================================================
// 2) 4-stage cp.async fp16 tensor GEMM. CTA 128x128, kstage=32, 2 CTAs/SM.
//    QKV mode: hidden column blocks -> fused GELU -> fp16.
// ============================================================================
#define GSTAGE 16384
#define GEMM_SMEM (4 * GSTAGE)   // 64 KB

template<bool QKV, bool ADD_RES>
__global__ __launch_bounds__(256, 2)
void tc_gemm4(const __half* __restrict__ Ah, int lda,
              const __half* __restrict__ Bh, int ldb,
              float* __restrict__ C, int ldc,
              const float* __restrict__ bias,
              const float* __restrict__ res,
              __half* __restrict__ Hh,
              int K) {
    extern __shared__ char gsm[];
    const uint32_t smb = smem_u32(gsm);

    const int tid = threadIdx.x;
    const int l = tid & 31, w = tid >> 5;
    const int wm = (w & 3) * 32;
    const int wn = (w >> 2) * 64;
    const int bm = blockIdx.x * 128, bn = blockIdx.y * 128;

    const int ar = tid >> 1;
    const int ac0 = (tid & 1) * 2;
    const int br = tid >> 3;
    const int bc0 = (tid & 7) * 2;

    float acc[2][8][4];
    #pragma unroll
    for (int mt = 0; mt < 2; mt++)
        #pragma unroll
        for (int nt = 0; nt < 8; nt++)
            #pragma unroll
            for (int e = 0; e < 4; e++) acc[mt][nt][e] = 0.f;

    const int nkb = K / 32;

    auto issue = [&](int stage, int k0) {
        uint32_t sb = smb + stage * GSTAGE;
        #pragma unroll
        for (int j = 0; j < 2; j++) {
            int c = ac0 + j;
            cp16(sb + ar * 64 + 16 * (c ^ ((ar >> 1) & 3)),
                 Ah + (size_t)(bm + ar) * lda + k0 + c * 8);
        }
        #pragma unroll
        for (int j = 0; j < 2; j++) {
            int c = bc0 + j;
            cp16(sb + 8192 + br * 256 + 16 * ((c & 8) | ((c ^ br) & 7)),
                 Bh + (size_t)(k0 + br) * ldb + bn + c * 8);
        }
    };

    issue(0, 0);  CP_COMMIT();
    issue(1, 32); CP_COMMIT();
    issue(2, 64); CP_COMMIT();

    for (int kb = 0; kb < nkb; kb++) {
        int rem = nkb - 1 - kb;
        if (rem >= 2)      { CP_WAIT2(); }
        else if (rem == 1) { CP_WAIT1(); }
        else               { CP_WAIT0(); }
        __syncthreads();
        if (kb + 3 < nkb) { issue((kb + 3) & 3, (kb + 3) * 32); CP_COMMIT(); }

        uint32_t sb = smb + (kb & 3) * GSTAGE;
        #pragma unroll
        for (int ks = 0; ks < 2; ks++) {
            uint32_t A[2][4];
            #pragma unroll
            for (int mt = 0; mt < 2; mt++) {
                int r = wm + mt * 16 + (l & 15);
                int c = ks * 2 + (l >> 4);
                ldsm_x4(A[mt][0], A[mt][1], A[mt][2], A[mt][3],
                        sb + r * 64 + 16 * (c ^ ((r >> 1) & 3)));
            }
            uint32_t B[4][4];
            #pragma unroll
            for (int p = 0; p < 4; p++) {
                int g = (w >> 2) * 4 + p;
                int kk = ks * 16 + (l & 7) + ((l >> 3) & 1) * 8;
                int c = 2 * g + ((l >> 4) & 1);
                ldsm_x4t(B[p][0], B[p][1], B[p][2], B[p][3],
                         sb + 8192 + kk * 256 + 16 * ((c & 8) | ((c ^ kk) & 7)));
            }
            #pragma unroll
            for (int p = 0; p < 4; p++)
                #pragma unroll
                for (int mt = 0; mt < 2; mt++) {
                    mma_f16(acc[mt][p * 2],     A[mt][0], A[mt][1], A[mt][2], A[mt][3], B[p][0], B[p][1]);
                    mma_f16(acc[mt][p * 2 + 1], A[mt][0], A[mt][1], A[mt][2], A[mt][3], B[p][2], B[p][3]);
                }
        }
    }

    // ---- epilogue ----
    if (QKV && bn >= QKV3) {
        #pragma unroll
        for (int mt = 0; mt < 2; mt++) {
            int row0 = bm + wm + mt * 16 + (l >> 2);
            #pragma unroll
            for (int nt = 0; nt < 8; nt++) {
                int col = bn + wn + nt * 8 + (l & 3) * 2;
                int hcol = col - QKV3;
                float b0 = bias[col], b1 = bias[col + 1];
                float* d = acc[mt][nt];
                *(uint32_t*)(Hh + (size_t)row0 * HIDDEN + hcol) =
                    pack_h(gelu_f(d[0] + b0), gelu_f(d[1] + b1));
                *(uint32_t*)(Hh + (size_t)(row0 + 8) * HIDDEN + hcol) =
                    pack_h(gelu_f(d[2] + b0), gelu_f(d[3] + b1));
            }
        }
    } else {
        #pragma unroll
        for (int mt = 0; mt < 2; mt++) {
            int row0 = bm + wm + mt * 16 + (l >> 2);
            #pragma unroll
            for (int nt = 0; nt < 8; nt++) {
                int col = bn + wn + nt * 8 + (l & 3) * 2;
                float b0 = bias[col], b1 = bias[col + 1];
                float* d = acc[mt][nt];
                float2 o0 = make_float2(d[0] + b0, d[1] + b1);
                float2 o1 = make_float2(d[2] + b0, d[3] + b1);
                if (ADD_RES) {
                    float2 r0 = *(const float2*)(res + (size_t)row0 * ldc + col);
                    float2 r1 = *(const float2*)(res + (size_t)(row0 + 8) * ldc + col);
                    o0.x += r0.x; o0.y += r0.y;
                    o1.x += r1.x; o1.y += r1.y;
                }
                *(float2*)(C + (size_t)row0 * ldc + col) = o0;
                *(float2*)(C + (size_t)(row0 + 8) * ldc + col) = o1;
            }
        }
    }
}

// ---------------- 3) q,k head-LN; -> head-major fp16 (q pre-scaled) ---------
__global__ void qkv_post_kernel(const float* __restrict__ qkv,
                                __half* __restrict__ qo, __half* __restrict__ ko,
                                __half* __restrict__ vo) {
    int gw   = (blockIdx.x * blockDim.x + threadIdx.x) >> 5;
    int lane = threadIdx.x & 31;
    int seg   = gw >> 16;        // 0=q, 1=k, 2=v
    int r     = gw & 65535;
    int token = r >> 4;
    int h     = r & 15;
    const float* base = qkv + (size_t)token * QKV3 + seg * D_MODEL + h * HEAD;
    float4 v = ((const float4*)base)[lane];
    if (seg < 2) {
        float s = warp_sum(v.x + v.y + v.z + v.w) * (1.f / HEAD);
        float d0 = v.x - s, d1 = v.y - s, d2 = v.z - s, d3 = v.w - s;
        float var = warp_sum(d0 * d0 + d1 * d1 + d2 * d2 + d3 * d3) * (1.f / HEAD);
        float rr = rsqrtf(var + 1e-5f);
        if (seg == 0) rr *= 0.08838834764831845f;   // fold 1/sqrt(HEAD) into q
        v = make_float4(d0 * rr, d1 * rr, d2 * rr, d3 * rr);
    }
    int b = token >> 11, tt = token & 2047;
    size_t o = ((((size_t)b * 16 + h) * 2048 + tt) * 128 + lane * 4) >> 2;
    __half* oh = (seg == 0) ? qo : (seg == 1) ? ko : vo;
    ((uint2*)oh)[o] = make_uint2(pack_h(v.x, v.y), pack_h(v.z, v.w));
}

// ============================================================================
// 4) flash v5: fp16 operands, 2 CTAs/SM, double-buffered BK=64 K/V tiles
// ============================================================================
#define FLASH_SMEM 98304   // Q 32KB + 2 stages x (K 16KB + V 16KB)

__global__ __launch_bounds__(256, 2)
void flash5_kernel(const __half* __restrict__ qh, const __half* __restrict__ kh,
                   const __half* __restrict__ vh, float* __restrict__ attn) {
    extern __shared__ char fsm[];
    const uint32_t sb = smem_u32(fsm);
    const int tid = threadIdx.x;
    const int l = tid & 31, w = tid >> 5;
    const int qt = (int)gridDim.x - 1 - (int)blockIdx.x;
    const int bh = blockIdx.y;
    const size_t hbase = (size_t)bh * 2048 * 128;

    // ---- issue Q (128 rows x 256B) ----
    {
        int row = tid >> 1, half = tid & 1;
        const __half* sq = qh + hbase + (size_t)(qt * 128 + row) * 128;
        #pragma unroll
        for (int j = 0; j < 8; j++) {
            int c = half * 8 + j;
            cp16(sb + row * 256 + 16 * ((c & 8) | ((c ^ row) & 7)), sq + c * 8);
        }
    }
    CP_COMMIT();
    auto issue_kv = [&](int stage, int kt) {
        uint32_t stb = sb + 32768 + stage * 32768;
        int r = tid >> 2, q4 = tid & 3;
        const __half* pk = kh + hbase + (size_t)(kt * 64 + r) * 128;
        const __half* pv = vh + hbase + (size_t)(kt * 64 + r) * 128;
        #pragma unroll
        for (int j = 0; j < 4; j++) {
            int c = q4 * 4 + j;
            uint32_t sw = r * 256 + 16 * ((c & 8) | ((c ^ r) & 7));
            cp16(stb + sw,         pk + c * 8);
            cp16(stb + 16384 + sw, pv + c * 8);
        }
    };
    issue_kv(0, 0);
    CP_COMMIT();

    float O_[16][4];
    #pragma unroll
    for (int t = 0; t < 16; t++)
        #pragma unroll
        for (int e = 0; e < 4; e++) O_[t][e] = 0.f;
    float M0 = -INFINITY, M1 = -INFINITY, L0 = 0.f, L1 = 0.f;
    const int ktmax = 2 * qt + 1;

    for (int kt = 0; kt <= ktmax; kt++) {
        CP_WAIT0();
        __syncthreads();
        if (kt < ktmax) { issue_kv((kt + 1) & 1, kt + 1); CP_COMMIT(); }

        uint32_t stb = sb + 32768 + (kt & 1) * 32768;

        // ---- S = Q K^T ----
        float s_[8][4];
        #pragma unroll
        for (int t = 0; t < 8; t++)
            #pragma unroll
            for (int e = 0; e < 4; e++) s_[t][e] = 0.f;

        #pragma unroll
        for (int ks = 0; ks < 8; ks++) {
            int qr = w * 16 + (l & 15);
            int qc = ks * 2 + (l >> 4);
            uint32_t q0, q1, q2, q3;
            ldsm_x4(q0, q1, q2, q3, sb + qr * 256 + 16 * ((qc & 8) | ((qc ^ qr) & 7)));
            #pragma unroll
            for (int g = 0; g < 4; g++) {
                int kr = g * 16 + (l & 7) + ((l >> 4) & 1) * 8;
                int kc = ks * 2 + ((l >> 3) & 1);
                uint32_t b0, b1, b2, b3;
                ldsm_x4(b0, b1, b2, b3, stb + kr * 256 + 16 * ((kc & 8) | ((kc ^ kr) & 7)));
                mma_f16(s_[2 * g],     q0, q1, q2, q3, b0, b1);
                mma_f16(s_[2 * g + 1], q0, q1, q2, q3, b2, b3);
            }
        }

        if (kt >= 2 * qt) {           // diagonal region: element mask
            int qr0 = qt * 128 + w * 16 + (l >> 2);
            int qr1 = qr0 + 8;
            #pragma unroll
            for (int t = 0; t < 8; t++) {
                int kc = kt * 64 + t * 8 + (l & 3) * 2;
                if (kc     > qr0) s_[t][0] = -INFINITY;
                if (kc + 1 > qr0) s_[t][1] = -INFINITY;
                if (kc     > qr1) s_[t][2] = -INFINITY;
                if (kc + 1 > qr1) s_[t][3] = -INFINITY;
            }
        }

        // ---- online softmax (rows owned by 4-lane groups) ----
        float m0 = -INFINITY, m1 = -INFINITY;
        #pragma unroll
        for (int t = 0; t < 8; t++) {
            m0 = fmaxf(m0, fmaxf(s_[t][0], s_[t][1]));
            m1 = fmaxf(m1, fmaxf(s_[t][2], s_[t][3]));
        }
        #pragma unroll
        for (int o = 1; o < 4; o <<= 1) {
            m0 = fmaxf(m0, __shfl_xor_sync(0xffffffffu, m0, o));
            m1 = fmaxf(m1, __shfl_xor_sync(0xffffffffu, m1, o));
        }
        float nm0 = fmaxf(M0, m0), nm1 = fmaxf(M1, m1);
        float corr0 = __expf(M0 - nm0), corr1 = __expf(M1 - nm1);
        M0 = nm0; M1 = nm1;

        float ps0 = 0.f, ps1 = 0.f;
        #pragma unroll
        for (int t = 0; t < 8; t++) {
            s_[t][0] = __expf(s_[t][0] - nm0); ps0 += s_[t][0];
            s_[t][1] = __expf(s_[t][1] - nm0); ps0 += s_[t][1];
            s_[t][2] = __expf(s_[t][2] - nm1); ps1 += s_[t][2];
            s_[t][3] = __expf(s_[t][3] - nm1); ps1 += s_[t][3];
        }
        #pragma unroll
        for (int o = 1; o < 4; o <<= 1) {
            ps0 += __shfl_xor_sync(0xffffffffu, ps0, o);
            ps1 += __shfl_xor_sync(0xffffffffu, ps1, o);
        }
        L0 = L0 * corr0 + ps0;
        L1 = L1 * corr1 + ps1;
        #pragma unroll
        for (int t = 0; t < 16; t++) {
            O_[t][0] *= corr0; O_[t][1] *= corr0;
            O_[t][2] *= corr1; O_[t][3] *= corr1;
        }

        // ---- O += P V ----
        #pragma unroll
        for (int s8 = 0; s8 < 4; s8++) {
            float* t0 = s_[2 * s8];
            float* t1 = s_[2 * s8 + 1];
            uint32_t ph[4];
            ph[0] = pack_h(t0[0], t0[1]);
            ph[1] = pack_h(t0[2], t0[3]);
            ph[2] = pack_h(t1[0], t1[1]);
            ph[3] = pack_h(t1[2], t1[3]);
            #pragma unroll
            for (int g = 0; g < 8; g++) {
                int vr = s8 * 16 + (l & 7) + ((l >> 3) & 1) * 8;
                int vc = 2 * g + ((l >> 4) & 1);
                uint32_t v0, v1, v2, v3;
                ldsm_x4t(v0, v1, v2, v3,
                         stb + 16384 + vr * 256 + 16 * ((vc & 8) | ((vc ^ vr) & 7)));
                mma_f16(O_[2 * g],     ph[0], ph[1], ph[2], ph[3], v0, v1);
                mma_f16(O_[2 * g + 1], ph[0], ph[1], ph[2], ph[3], v2, v3);
            }
        }
    }

    // ---- epilogue: attn = O / L ----
    int b = bh >> 4, h = bh & 15;
    float inv0 = 1.f / L0, inv1 = 1.f / L1;
    int token = qt * 128 + w * 16 + (l >> 2);
    float* row0p = attn + (size_t)(b * TT + token) * D_MODEL + h * HEAD;
    float* row1p = row0p + (size_t)8 * D_MODEL;
    #pragma unroll
    for (int t = 0; t < 16; t++) {
        int col = t * 8 + (l & 3) * 2;
        *(float2*)(row0p + col) = make_float2(O_[t][0] * inv0, O_[t][1] * inv0);
        *(float2*)(row1p + col) = make_float2(O_[t][2] * inv1, O_[t][3] * inv1);
    }
}

// ---------------- 5) out += attn --------------------------------------------
__global__ void attn_add_kernel(float* __restrict__ out, const float* __restrict__ attn) {
    int idx = blockIdx.x * blockDim.x + threadIdx.x;
    float4 o = ((float4*)out)[idx];
    float4 a = ((const float4*)attn)[idx];
    o.x += a.x; o.y += a.y; o.z += a.z; o.w += a.w;
    ((float4*)out)[idx] = o;
}

// ---------------- launch ----------------------------------------------------
extern "C" void kernel_launch(void* const* d_in, const int* in_sizes, int n_in,
                              void* d_out, int out_size) {
    const float* inputs = (const float*)d_in[0];
    const float* W_qkv  = (const float*)d_in[1];
    const float* b_qkv  = (const float*)d_in[2];
    const float* W_mlp  = (const float*)d_in[3];
    const float* b_mlp  = (const float*)d_in[4];
    float* out = (float*)d_out;

    void *pq, *px, *pwq, *pwm, *ph, *pqo, *pko, *pvo;
    cudaGetSymbolAddress(&pq,  g_qkv);
    cudaGetSymbolAddress(&px,  g_x);
    cudaGetSymbolAddress(&pwq, g_wq);
    cudaGetSymbolAddress(&pwm, g_wm);
    cudaGetSymbolAddress(&ph,  g_h);
    cudaGetSymbolAddress(&pqo, g_q);
    cudaGetSymbolAddress(&pko, g_k);
    cudaGetSymbolAddress(&pvo, g_v);
    float* gq = (float*)pq;
    float* gattn = gq;   // reuse q/k/v fp32 scratch as attention output

    cudaFuncSetAttribute(tc_gemm4<true, false>,
                         cudaFuncAttributeMaxDynamicSharedMemorySize, GEMM_SMEM);
    cudaFuncSetAttribute(tc_gemm4<false, true>,
                         cudaFuncAttributeMaxDynamicSharedMemorySize, GEMM_SMEM);
    cudaFuncSetAttribute(flash5_kernel,
                         cudaFuncAttributeMaxDynamicSharedMemorySize, FLASH_SMEM);

    cudaStream_t s1;
    cudaStreamCreateWithFlags(&s1, cudaStreamNonBlocking);
    cudaEvent_t e0, e1;
    cudaEventCreateWithFlags(&e0, cudaEventDisableTiming);
    cudaEventCreateWithFlags(&e1, cudaEventDisableTiming);

    // 0) convert weights to fp16
    convert_kernel<<<(D_MODEL * QKV_OUT / 4) / 256, 256>>>(W_qkv, (__half*)pwq);
    convert_kernel<<<(HIDDEN * D_MODEL / 4) / 256, 256>>>(W_mlp, (__half*)pwm);

    // 1) LN(inputs) -> fp16
    ln_input_kernel<<<BT, 256>>>(inputs, (__half*)px);

    // 2) qkv GEMM: q,k,v -> fp32 g_qkv; hidden -> fused GELU fp16
    tc_gemm4<true, false><<<dim3(BT / 128, QKV_OUT / 128), 256, GEMM_SMEM>>>(
        (__half*)px, D_MODEL, (__half*)pwq, QKV_OUT,
        gq, QKV3, b_qkv, nullptr, (__half*)ph, D_MODEL);

    // ---- fork: MLP on s1 ----
    cudaEventRecord(e0, 0);
    cudaStreamWaitEvent(s1, e0, 0);
    tc_gemm4<false, true><<<dim3(BT / 128, D_MODEL / 128), 256, GEMM_SMEM, s1>>>(
        (__half*)ph, HIDDEN, (__half*)pwm, D_MODEL,
        out, D_MODEL, b_mlp, inputs, nullptr, HIDDEN);
    cudaEventRecord(e1, s1);

    // ---- main stream: attention branch ----
    // 3) q,k head-LN (q pre-scaled); head-major fp16
    qkv_post_kernel<<<(3 * 65536) / 8, 256>>>(
        gq, (__half*)pqo, (__half*)pko, (__half*)pvo);

    // 4) attn = attention(q, k, v)  (g_qkv no longer needed -> reuse as scratch)
    flash5_kernel<<<dim3(TT / 128, BB * NUM_HEADS), 256, FLASH_SMEM>>>(
        (__half*)pqo, (__half*)pko, (__half*)pvo, gattn);

    // ---- join, then out += attn ----
    cudaStreamWaitEvent(0, e1, 0);
    attn_add_kernel<<<(BT * D_MODEL / 4) / 256, 256>>>(out, gattn);
}